// round 15
// baseline (speedup 1.0000x reference)
#include <cuda_runtime.h>
#include <cuda_fp16.h>
#include <math.h>
#include <stdint.h>

// ---------------- problem constants ----------------
#define DM   1024
#define LL   2048
#define BBATCH 2
#define DI   2048
#define NSTATE 16
#define RDT  64
#define XPW  96
#define MROWS (BBATCH*LL)
#define NCH  32
#define CLEN (LL/NCH)

// ---------------- scratch (offsets in floats) ----------------
#define O_Z      ((size_t)0)                           // [MROWS, DI]
#define O_XMT    (O_Z      + (size_t)MROWS*DI)         // [DI, MROWS]
#define O_XCT    (O_XMT    + (size_t)DI*MROWS)         // [DI, MROWS]
#define O_DTT    (O_XCT    + (size_t)DI*MROWS)         // [DI, MROWS]
#define O_XDBL   (O_DTT    + (size_t)DI*MROWS)         // [MROWS, 96]
#define O_WX     (O_XDBL   + (size_t)MROWS*XPW)        // tf32 [DI][96]
#define O_XPART  (O_WX     + (size_t)DI*XPW)           // [4][MROWS][96]
#define O_XN16   (O_XPART  + (size_t)4*MROWS*XPW)      // half [MROWS][DM]
#define O_WIN16  (O_XN16   + (size_t)MROWS*DM/2)       // half [2DI][DM]
#define O_WOUT16 (O_WIN16  + (size_t)DM*2*DI/2)        // half [DM][DI]
#define O_WDT16  (O_WOUT16 + (size_t)DI*DM/2)          // half [DI][RDT]
#define O_YY16   (O_WDT16  + (size_t)DI*RDT/2)         // half [MROWS][DI]
#define O_XDBL16 (O_YY16   + (size_t)MROWS*DI/2)       // half [MROWS][64]
#define O_APROD  (O_XDBL16 + (size_t)MROWS*64/2)
#define O_BST    (O_APROD  + (size_t)BBATCH*DI*NCH*16)
#define O_HIN    (O_BST    + (size_t)BBATCH*DI*NCH*16)
#define O_TOTAL  (O_HIN    + (size_t)BBATCH*DI*NCH*16)

__device__ __align__(16) float g_scratch[O_TOTAL];

#define OOUT_SSM  ((size_t)MROWS*DM)
#define OOUT_CONV (OOUT_SSM + (size_t)BBATCH*DI*NSTATE)

__device__ __forceinline__ float siluf(float v) { return v / (1.0f + __expf(-v)); }

__device__ __forceinline__ uint32_t f2tf(float f) {
    uint32_t u;
    asm("cvt.rna.tf32.f32 %0, %1;" : "=r"(u) : "f"(f));
    return u;
}

#define CP16(saddr, gptr) \
    asm volatile("cp.async.cg.shared.global [%0], [%1], 16;" :: "r"(saddr), "l"(gptr))

__device__ __forceinline__ void ldsm4(uint32_t& r0, uint32_t& r1, uint32_t& r2,
                                      uint32_t& r3, uint32_t addr) {
    asm volatile("ldmatrix.sync.aligned.m8n8.x4.shared.b16 {%0,%1,%2,%3}, [%4];"
                 : "=r"(r0), "=r"(r1), "=r"(r2), "=r"(r3) : "r"(addr));
}

// ================= fp16 HMMA GEMM core (device) ==============================
// 64x64 warp tiles, BM=BN=128, BK=32, 3-stage ring, 1 sync/tile, 128 threads.
template<int EPI>
__device__ __forceinline__ void hgemm_body(
      const __half* __restrict__ A, int lda,
      const __half* __restrict__ Bt, int ldb,
      float* __restrict__ C, int ldc,
      int K, int row0, int col0,
      const float* __restrict__ bias,
      const float* __restrict__ resid, int ldr,
      const float* __restrict__ scale_ptr,
      char* sm) {
    constexpr int ROWB = 80;
    constexpr int TILEB = 128 * ROWB;
    constexpr int STAGEB = 2 * TILEB;

    const int tid  = threadIdx.x;
    const int lane = tid & 31;
    const int wid  = tid >> 5;
    const int wm0 = (wid >> 1) * 64;
    const int wn0 = (wid & 1) * 64;
    const int g = lane >> 2;
    const int t = lane & 3;

    uint32_t sBase = (uint32_t)__cvta_generic_to_shared(sm);

    const int a_row  = wm0 + (lane & 7) + ((lane >> 3) & 1) * 8;
    const int a_coff = ((lane >> 4) & 1) * 16;
    const int b_row  = wn0 + (lane & 7) + ((lane >> 4) & 1) * 8;
    const int b_coff = ((lane >> 3) & 1) * 16;
    const uint32_t aOff = (uint32_t)(a_row * ROWB + a_coff);
    const uint32_t bOff = (uint32_t)(TILEB + b_row * ROWB + b_coff);

    auto issueCopy = [&](int st, int k0) {
        #pragma unroll
        for (int p = 0; p < 4; p++) {
            int e = tid + p * 128;
            int r = e >> 2, c = e & 3;
            uint32_t dst = sBase + (uint32_t)(st * STAGEB + r * ROWB + c * 16);
            CP16(dst, A + (size_t)(row0 + r) * lda + k0 + c * 8);
            CP16(dst + TILEB, Bt + (size_t)(col0 + r) * ldb + k0 + c * 8);
        }
        asm volatile("cp.async.commit_group;");
    };

    float acc[4][8][4];
    #pragma unroll
    for (int mi = 0; mi < 4; mi++)
        #pragma unroll
        for (int ni = 0; ni < 8; ni++)
            #pragma unroll
            for (int e = 0; e < 4; e++) acc[mi][ni][e] = 0.f;

    const int nk = K / 32;
    issueCopy(0, 0);
    if (nk > 1) issueCopy(1, 32);

    for (int kt = 0; kt < nk; kt++) {
        if (kt + 1 < nk)
            asm volatile("cp.async.wait_group 1;");
        else
            asm volatile("cp.async.wait_group 0;");
        __syncthreads();
        if (kt + 2 < nk) issueCopy((kt + 2) % 3, (kt + 2) * 32);

        uint32_t stBase = sBase + (uint32_t)((kt % 3) * STAGEB);
        #pragma unroll
        for (int ks = 0; ks < 2; ks++) {
            uint32_t af[4][4], bf[8][2];
            #pragma unroll
            for (int mi = 0; mi < 4; mi++)
                ldsm4(af[mi][0], af[mi][1], af[mi][2], af[mi][3],
                      stBase + aOff + mi * (16 * ROWB) + ks * 32);
            #pragma unroll
            for (int nq = 0; nq < 4; nq++)
                ldsm4(bf[2 * nq][0], bf[2 * nq][1], bf[2 * nq + 1][0], bf[2 * nq + 1][1],
                      stBase + bOff + nq * (16 * ROWB) + ks * 32);
            #pragma unroll
            for (int mi = 0; mi < 4; mi++)
                #pragma unroll
                for (int ni = 0; ni < 8; ni++)
                    asm volatile(
                        "mma.sync.aligned.m16n8k16.row.col.f32.f16.f16.f32 "
                        "{%0,%1,%2,%3}, {%4,%5,%6,%7}, {%8,%9}, {%0,%1,%2,%3};"
                        : "+f"(acc[mi][ni][0]), "+f"(acc[mi][ni][1]),
                          "+f"(acc[mi][ni][2]), "+f"(acc[mi][ni][3])
                        : "r"(af[mi][0]), "r"(af[mi][1]),
                          "r"(af[mi][2]), "r"(af[mi][3]),
                          "r"(bf[ni][0]), "r"(bf[ni][1]));
        }
    }

    float scl = (EPI == 2) ? scale_ptr[0] : 1.0f;
    #pragma unroll
    for (int mi = 0; mi < 4; mi++) {
        int r0 = row0 + wm0 + mi * 16 + g;
        #pragma unroll
        for (int ni = 0; ni < 8; ni++) {
            int c0n = col0 + wn0 + ni * 8 + t * 2;
            #pragma unroll
            for (int e = 0; e < 4; e++) {
                int rr = r0 + ((e >= 2) ? 8 : 0);
                int cc = c0n + (e & 1);
                float v = acc[mi][ni][e];
                if (EPI == 1) {
                    v += bias[cc];
                    v = (v > 20.0f) ? v : log1pf(__expf(v));
                } else if (EPI == 2) {
                    v = scl * v + resid[(size_t)rr * ldr + cc];
                } else if (EPI == 3) {
                    v += bias[rr];
                    v = (v > 20.0f) ? v : log1pf(__expf(v));
                }
                C[(size_t)rr * ldc + cc] = v;
            }
        }
    }
}

template<int EPI>
__global__ void __launch_bounds__(128, 3)
hgemm(const __half* __restrict__ A, int lda,
      const __half* __restrict__ Bt, int ldb,
      float* __restrict__ C, int ldc,
      int M, int N, int K,
      const float* __restrict__ bias,
      const float* __restrict__ resid, int ldr,
      const float* __restrict__ scale_ptr) {
    extern __shared__ __align__(16) char sm[];
    hgemm_body<EPI>(A, lda, Bt, ldb, C, ldc, K,
                    blockIdx.y * 128, blockIdx.x * 128,
                    bias, resid, ldr, scale_ptr, sm);
}

// fused x-GEMM + z-GEMM: 1024 blocks. First 512: xmT[d][tok] = Wx . xn^T.
// Last 512: z[tok][d] = xn . Wz^T.
__global__ void __launch_bounds__(128, 3)
hgemm_xz(const __half* __restrict__ xn16,
         const __half* __restrict__ w_in16,
         float* __restrict__ xmT, float* __restrict__ z) {
    extern __shared__ __align__(16) char sm[];
    int bid = blockIdx.x;
    if (bid < 512) {
        // grid (MROWS/128=32) x (DI/128=16)
        int bx = bid & 31, by = bid >> 5;
        hgemm_body<0>(w_in16, DM, xn16, DM, xmT, MROWS, DM,
                      by * 128, bx * 128, nullptr, nullptr, 0, nullptr, sm);
    } else {
        bid -= 512;
        // grid (DI/128=16) x (MROWS/128=32)
        int bx = bid & 15, by = bid >> 4;
        hgemm_body<0>(xn16, DM, w_in16 + (size_t)DI * DM, DM, z, DI, DM,
                      by * 128, bx * 128, nullptr, nullptr, 0, nullptr, sm);
    }
}

// ---------------- weight convert+transpose to half --------------------------
__global__ void cvtT_half_kernel(const float* __restrict__ in, __half* __restrict__ out,
                                 int R, int C) {
    __shared__ float tile[32][33];
    int c0 = blockIdx.x * 32, r0 = blockIdx.y * 32;
    #pragma unroll
    for (int j = 0; j < 32; j += 8)
        tile[threadIdx.y + j][threadIdx.x] =
            in[(size_t)(r0 + threadIdx.y + j) * C + c0 + threadIdx.x];
    __syncthreads();
    #pragma unroll
    for (int j = 0; j < 32; j += 8)
        out[(size_t)(c0 + threadIdx.y + j) * R + r0 + threadIdx.x] =
            __float2half_rn(tile[threadIdx.x][threadIdx.y + j]);
}

// ---------------- tf32 convert (x_proj weight) -------------------------------
__global__ void cvt_wx_kernel(const float* __restrict__ s, float* __restrict__ d, int n) {
    int i = (blockIdx.x * 256 + threadIdx.x) * 4;
    if (i < n) {
        float4 v = *reinterpret_cast<const float4*>(s + i);
        uint4 u = make_uint4(f2tf(v.x), f2tf(v.y), f2tf(v.z), f2tf(v.w));
        *reinterpret_cast<uint4*>(d + i) = u;
    }
}

// ---------------- LayerNorm (emits half) -------------------------------------
__global__ void ln_kernel(const float* __restrict__ x,
                          const float* __restrict__ w,
                          const float* __restrict__ b,
                          __half* __restrict__ xn16) {
    int row = blockIdx.x;
    const float4* px = reinterpret_cast<const float4*>(x + (size_t)row * DM);
    float4 v = px[threadIdx.x];
    float s  = v.x + v.y + v.z + v.w;
    float sq = v.x*v.x + v.y*v.y + v.z*v.z + v.w*v.w;
    #pragma unroll
    for (int o = 16; o; o >>= 1) {
        s  += __shfl_xor_sync(0xffffffffu, s,  o);
        sq += __shfl_xor_sync(0xffffffffu, sq, o);
    }
    __shared__ float ss[8], sqs[8];
    __shared__ float s_mu, s_rs;
    int wid = threadIdx.x >> 5, lid = threadIdx.x & 31;
    if (lid == 0) { ss[wid] = s; sqs[wid] = sq; }
    __syncthreads();
    if (threadIdx.x == 0) {
        float S = 0.f, Q = 0.f;
        #pragma unroll
        for (int i = 0; i < 8; i++) { S += ss[i]; Q += sqs[i]; }
        float m = S * (1.0f / DM);
        float var = Q * (1.0f / DM) - m * m;
        s_mu = m;
        s_rs = rsqrtf(var + 1e-5f);
    }
    __syncthreads();
    float m = s_mu, r = s_rs;
    float4 wv = reinterpret_cast<const float4*>(w)[threadIdx.x];
    float4 bv = reinterpret_cast<const float4*>(b)[threadIdx.x];
    __half2 h01 = __floats2half2_rn((v.x - m) * r * wv.x + bv.x,
                                    (v.y - m) * r * wv.y + bv.y);
    __half2 h23 = __floats2half2_rn((v.z - m) * r * wv.z + bv.z,
                                    (v.w - m) * r * wv.w + bv.w);
    uint2 st;
    st.x = *reinterpret_cast<uint32_t*>(&h01);
    st.y = *reinterpret_cast<uint32_t*>(&h23);
    *reinterpret_cast<uint2*>(xn16 + (size_t)row * DM + threadIdx.x * 4) = st;
}

// ---------------- x_proj split-K kernel (tf32, reads xcT [d][MROWS]) ---------
__global__ void __launch_bounds__(256, 2)
xproj_kernel(const float* __restrict__ xcT,
             const float* __restrict__ Wx,
             float* __restrict__ part) {
    constexpr int BK = 16, SAT = 136, SBX = 104;
    constexpr int ASZ = BK * SAT, BSZ = BK * SBX;
    __shared__ float At[3 * ASZ];
    __shared__ float Bt[3 * BSZ];

    const int tid  = threadIdx.x;
    const int lane = tid & 31;
    const int wid  = tid >> 5;
    const int wm0 = (wid >> 2) * 64;
    const int wn0 = (wid & 3) * 24;
    const int g = lane >> 2, t = lane & 3;

    const int tok0 = blockIdx.x * 128;
    const int kbase = blockIdx.y * (DI / 4);

    uint32_t aSm = (uint32_t)__cvta_generic_to_shared(At);
    uint32_t bSm = (uint32_t)__cvta_generic_to_shared(Bt);

    auto issueCopy = [&](int st, int k0) {
        int kg = kbase + k0;
        #pragma unroll
        for (int p = 0; p < 2; p++) {
            int idx = tid + p * 256;
            int r = idx >> 5, c = idx & 31;
            CP16(aSm + (uint32_t)(st * ASZ + r * SAT + c * 4) * 4,
                 xcT + (size_t)(kg + r) * MROWS + tok0 + c * 4);
        }
        #pragma unroll
        for (int p = 0; p < 2; p++) {
            int idx = tid + p * 256;
            if (idx < 384) {
                int r = idx / 24, c = idx % 24;
                CP16(bSm + (uint32_t)(st * BSZ + r * SBX + c * 4) * 4,
                     Wx + (size_t)(kg + r) * XPW + c * 4);
            }
        }
        asm volatile("cp.async.commit_group;");
    };

    float acc[4][3][4];
    #pragma unroll
    for (int mi = 0; mi < 4; mi++)
        #pragma unroll
        for (int ni = 0; ni < 3; ni++)
            #pragma unroll
            for (int e = 0; e < 4; e++) acc[mi][ni][e] = 0.f;

    const int nk = (DI / 4) / BK;
    issueCopy(0, 0);
    issueCopy(1, BK);

    for (int kt = 0; kt < nk; kt++) {
        if (kt + 1 < nk)
            asm volatile("cp.async.wait_group 1;");
        else
            asm volatile("cp.async.wait_group 0;");
        __syncthreads();
        if (kt + 2 < nk) issueCopy((kt + 2) % 3, (kt + 2) * BK);

        const float* Af = At + (kt % 3) * ASZ;
        const float* Bf = Bt + (kt % 3) * BSZ;
        #pragma unroll
        for (int ks = 0; ks < 2; ks++) {
            uint32_t af[4][4], bf[3][2];
            #pragma unroll
            for (int mi = 0; mi < 4; mi++) {
                const float* pa = Af + (ks * 8 + t) * SAT + wm0 + mi * 16 + g;
                af[mi][0] = f2tf(pa[0]);
                af[mi][1] = f2tf(pa[8]);
                af[mi][2] = f2tf(pa[4 * SAT]);
                af[mi][3] = f2tf(pa[4 * SAT + 8]);
            }
            #pragma unroll
            for (int ni = 0; ni < 3; ni++) {
                const float* pb = Bf + (ks * 8 + t) * SBX + wn0 + ni * 8 + g;
                bf[ni][0] = __float_as_uint(pb[0]);
                bf[ni][1] = __float_as_uint(pb[4 * SBX]);
            }
            #pragma unroll
            for (int mi = 0; mi < 4; mi++)
                #pragma unroll
                for (int ni = 0; ni < 3; ni++)
                    asm volatile(
                        "mma.sync.aligned.m16n8k8.row.col.f32.tf32.tf32.f32 "
                        "{%0,%1,%2,%3}, {%4,%5,%6,%7}, {%8,%9}, {%0,%1,%2,%3};"
                        : "+f"(acc[mi][ni][0]), "+f"(acc[mi][ni][1]),
                          "+f"(acc[mi][ni][2]), "+f"(acc[mi][ni][3])
                        : "r"(af[mi][0]), "r"(af[mi][1]),
                          "r"(af[mi][2]), "r"(af[mi][3]),
                          "r"(bf[ni][0]), "r"(bf[ni][1]));
        }
        __syncthreads();
    }

    float* po = part + (size_t)blockIdx.y * MROWS * XPW;
    #pragma unroll
    for (int mi = 0; mi < 4; mi++) {
        int r0 = tok0 + wm0 + mi * 16 + g;
        #pragma unroll
        for (int ni = 0; ni < 3; ni++) {
            int c0n = wn0 + ni * 8 + t * 2;
            #pragma unroll
            for (int e = 0; e < 4; e++) {
                int rr = r0 + ((e >= 2) ? 8 : 0);
                int cc = c0n + (e & 1);
                po[(size_t)rr * XPW + cc] = acc[mi][ni][e];
            }
        }
    }
}

// ---------------- reduce 4 x_proj partials -----------------------------------
__global__ void xdbl_reduce_kernel(const float* __restrict__ part,
                                   float* __restrict__ xdbl,
                                   __half* __restrict__ xdbl16) {
    constexpr size_t N4 = (size_t)MROWS * XPW / 4;
    size_t i = (size_t)blockIdx.x * 256 + threadIdx.x;
    if (i < N4) {
        const float4* p = reinterpret_cast<const float4*>(part);
        float4 a = p[i], b = p[i + N4], c = p[i + 2 * N4], d = p[i + 3 * N4];
        float4 r = make_float4(a.x + b.x + c.x + d.x, a.y + b.y + c.y + d.y,
                               a.z + b.z + c.z + d.z, a.w + b.w + c.w + d.w);
        reinterpret_cast<float4*>(xdbl)[i] = r;
        size_t row = (i * 4) / XPW;
        int col = (int)((i * 4) % XPW);
        if (col < RDT) {
            __half2 h01 = __floats2half2_rn(r.x, r.y);
            __half2 h23 = __floats2half2_rn(r.z, r.w);
            uint2 st;
            st.x = *reinterpret_cast<uint32_t*>(&h01);
            st.y = *reinterpret_cast<uint32_t*>(&h23);
            *reinterpret_cast<uint2*>(xdbl16 + row * RDT + col) = st;
        }
    }
}

// ---------------- depthwise causal conv (float4), [d][MROWS] layout ----------
__global__ void conv_silu_kernel(const float* __restrict__ in,
                                 float* __restrict__ out,
                                 const float* __restrict__ cw,
                                 const float* __restrict__ cb,
                                 float* __restrict__ outp) {
    int chb = blockIdx.x;
    int d  = chb / BBATCH;
    int b  = chb % BBATCH;
    const float* pin = in + (size_t)d * MROWS + b * LL;
    float* pout = out + (size_t)d * MROWS + b * LL;
    float w0 = cw[d * 4 + 0], w1 = cw[d * 4 + 1], w2 = cw[d * 4 + 2], w3 = cw[d * 4 + 3];
    float bias = cb[d];
    for (int base = threadIdx.x * 4; base < LL; base += blockDim.x * 4) {
        float4 cur = *reinterpret_cast<const float4*>(pin + base);
        float4 prev = (base >= 4) ? *reinterpret_cast<const float4*>(pin + base - 4)
                                  : make_float4(0.f, 0.f, 0.f, 0.f);
        float o0 = bias + w0 * prev.y + w1 * prev.z + w2 * prev.w + w3 * cur.x;
        float o1 = bias + w0 * prev.z + w1 * prev.w + w2 * cur.x + w3 * cur.y;
        float o2 = bias + w0 * prev.w + w1 * cur.x + w2 * cur.y + w3 * cur.z;
        float o3 = bias + w0 * cur.x  + w1 * cur.y + w2 * cur.z + w3 * cur.w;
        *reinterpret_cast<float4*>(pout + base) =
            make_float4(siluf(o0), siluf(o1), siluf(o2), siluf(o3));
    }
    if (threadIdx.x < 3)
        outp[OOUT_CONV + ((size_t)b * DI + d) * 3 + threadIdx.x] = pin[LL - 3 + threadIdx.x];
}

// ---------------- chunked scan common helpers -------------------------------
struct ScanCtx {
    float A0, A1;
    bool fastok;
    bool b1, b2, b4;
};

__device__ __forceinline__ ScanCtx scan_ctx(const float* A_log, int d, int sub) {
    ScanCtx c;
    float2 Al = *reinterpret_cast<const float2*>(&A_log[d * NSTATE + sub * 2]);
    float a0e = __expf(Al.x);
    float a1e = __expf(Al.y);
    c.A0 = -a0e; c.A1 = -a1e;
    float fi0 = (float)(2 * sub + 1);
    bool ok = (fabsf(a0e - fi0) < 1e-4f) && (fabsf(a1e - (fi0 + 1.0f)) < 1e-4f);
    c.fastok = __all_sync(0xffffffffu, ok);
    c.b1 = (sub & 1); c.b2 = (sub & 2); c.b4 = (sub & 4);
    return c;
}

__device__ __forceinline__ void scan_da(const ScanCtx& c, float dt,
                                        float& da0, float& da1) {
    if (c.fastok) {
        float E  = __expf(-dt);
        float E2 = E * E;
        float E4 = E2 * E2;
        float E8 = E4 * E4;
        float q = E;
        if (c.b1) q *= E2;
        if (c.b2) q *= E4;
        if (c.b4) q *= E8;
        da0 = q;
        da1 = q * E;
    } else {
        da0 = __expf(c.A0 * dt);
        da1 = __expf(c.A1 * dt);
    }
}

// ---------------- scan phase 1 ------------------------------------------------
__global__ void __launch_bounds__(256)
scan_phase1(const float* __restrict__ dtT, const float* __restrict__ xT,
            const float* __restrict__ xdbl, const float* __restrict__ A_log,
            float* __restrict__ aprod, float* __restrict__ bst) {
    int tid = threadIdx.x;
    int ch  = blockIdx.x * 32 + (tid >> 3);
    int sub = tid & 7;
    int ck  = blockIdx.y;
    int b   = ch / DI;
    int d   = ch & (DI - 1);
    ScanCtx cx = scan_ctx(A_log, d, sub);

    const float* pdt = dtT + (size_t)d * MROWS + b * LL + ck * CLEN;
    const float* px  = xT  + (size_t)d * MROWS + b * LL + ck * CLEN;
    const float* pbc = xdbl + ((size_t)b * LL + ck * CLEN) * XPW;

    float h0 = 0.f, h1 = 0.f, ap0 = 1.f, ap1 = 1.f;
    for (int t0 = 0; t0 < CLEN; t0 += 8) {
        float4 dtA = *reinterpret_cast<const float4*>(pdt + t0);
        float4 dtB = *reinterpret_cast<const float4*>(pdt + t0 + 4);
        float4 xvA = *reinterpret_cast<const float4*>(px + t0);
        float4 xvB = *reinterpret_cast<const float4*>(px + t0 + 4);
        float dts[8] = {dtA.x, dtA.y, dtA.z, dtA.w, dtB.x, dtB.y, dtB.z, dtB.w};
        float xvs[8] = {xvA.x, xvA.y, xvA.z, xvA.w, xvB.x, xvB.y, xvB.z, xvB.w};
        #pragma unroll
        for (int j = 0; j < 8; j++) {
            float dt = dts[j];
            const float* prow = pbc + (size_t)(t0 + j) * XPW;
            float2 Bv = *reinterpret_cast<const float2*>(prow + RDT + sub * 2);
            float da0, da1;
            scan_da(cx, dt, da0, da1);
            float dx = dt * xvs[j];
            h0 = fmaf(da0, h0, Bv.x * dx);
            h1 = fmaf(da1, h1, Bv.y * dx);
            ap0 *= da0;
            ap1 *= da1;
        }
    }
    size_t o = ((size_t)ch * NCH + ck) * NSTATE + sub * 2;
    *reinterpret_cast<float2*>(bst + o)   = make_float2(h0, h1);
    *reinterpret_cast<float2*>(aprod + o) = make_float2(ap0, ap1);
}

// ---------------- scan phase 2 ------------------------------------------------
__global__ void scan_phase2(const float* __restrict__ aprod,
                            const float* __restrict__ bst,
                            float* __restrict__ hin) {
    int idx = blockIdx.x * 256 + threadIdx.x;
    if (idx < BBATCH * DI * NSTATE) {
        int ch = idx >> 4;
        int n  = idx & 15;
        float h = 0.f;
        #pragma unroll
        for (int c = 0; c < NCH; c++) {
            size_t o = ((size_t)ch * NCH + c) * NSTATE + n;
            hin[o] = h;
            h = fmaf(aprod[o], h, bst[o]);
        }
    }
}

// ---------------- scan phase 3: seeded scan + fused gate ----------------------
__global__ void __launch_bounds__(256)
scan_phase3(const float* __restrict__ dtT, const float* __restrict__ xT,
            const float* __restrict__ xdbl, const float* __restrict__ A_log,
            const float* __restrict__ hin, const float* __restrict__ Dp,
            const float* __restrict__ z,
            __half* __restrict__ yy16, float* __restrict__ outp) {
    __shared__ float ysm[32][33];
    __shared__ float xsm[32][33];
    __shared__ float dsm[32];

    int tid = threadIdx.x;
    int cl  = tid >> 3;
    int sub = tid & 7;
    int ck  = blockIdx.y;
    int chBase = blockIdx.x * 32;
    int ch  = chBase + cl;
    int b   = ch / DI;
    int d   = ch & (DI - 1);
    int d0  = chBase & (DI - 1);
    ScanCtx cx = scan_ctx(A_log, d, sub);

    if (tid < 32) dsm[tid] = Dp[d0 + tid];

    const float* pdt = dtT + (size_t)d * MROWS + b * LL + ck * CLEN;
    const float* px  = xT  + (size_t)d * MROWS + b * LL + ck * CLEN;
    const float* pbc = xdbl + ((size_t)b * LL + ck * CLEN) * XPW;

    float2 h = *reinterpret_cast<const float2*>(
        hin + ((size_t)ch * NCH + ck) * NSTATE + sub * 2);
    float h0 = h.x, h1 = h.y;
    __syncthreads();

    for (int tb = 0; tb < CLEN; tb += 32) {
        #pragma unroll
        for (int g8 = 0; g8 < 4; g8++) {
            int t0 = tb + g8 * 8;
            float4 dtA = *reinterpret_cast<const float4*>(pdt + t0);
            float4 dtB = *reinterpret_cast<const float4*>(pdt + t0 + 4);
            float4 xvA = *reinterpret_cast<const float4*>(px + t0);
            float4 xvB = *reinterpret_cast<const float4*>(px + t0 + 4);
            float dts[8] = {dtA.x, dtA.y, dtA.z, dtA.w, dtB.x, dtB.y, dtB.z, dtB.w};
            float xvs[8] = {xvA.x, xvA.y, xvA.z, xvA.w, xvB.x, xvB.y, xvB.z, xvB.w};
            float pj[8];
            #pragma unroll
            for (int j = 0; j < 8; j++) {
                float dt = dts[j];
                const float* prow = pbc + (size_t)(t0 + j) * XPW;
                float2 Bv = *reinterpret_cast<const float2*>(prow + RDT + sub * 2);
                float2 Cv = *reinterpret_cast<const float2*>(prow + RDT + NSTATE + sub * 2);
                float da0, da1;
                scan_da(cx, dt, da0, da1);
                float dx = dt * xvs[j];
                h0 = fmaf(da0, h0, Bv.x * dx);
                h1 = fmaf(da1, h1, Bv.y * dx);
                pj[j] = fmaf(h0, Cv.x, h1 * Cv.y);
            }
            #pragma unroll
            for (int off = 4; off; off >>= 1)
                #pragma unroll
                for (int j = 0; j < 8; j++)
                    pj[j] += __shfl_xor_sync(0xffffffffu, pj[j], off, 8);
            if (sub == 0) {
                int r = g8 * 8;
                #pragma unroll
                for (int j = 0; j < 8; j++) {
                    ysm[r + j][cl] = pj[j];
                    xsm[r + j][cl] = xvs[j];
                }
            }
        }
        __syncthreads();
        {
            int r = tid >> 3;
            int c = (tid & 7) * 4;
            size_t row = (size_t)b * LL + ck * CLEN + tb + r;
            float4 z4 = *reinterpret_cast<const float4*>(z + row * DI + d0 + c);
            float v0 = (ysm[r][c + 0] + xsm[r][c + 0] * dsm[c + 0]) * siluf(z4.x);
            float v1 = (ysm[r][c + 1] + xsm[r][c + 1] * dsm[c + 1]) * siluf(z4.y);
            float v2 = (ysm[r][c + 2] + xsm[r][c + 2] * dsm[c + 2]) * siluf(z4.z);
            float v3 = (ysm[r][c + 3] + xsm[r][c + 3] * dsm[c + 3]) * siluf(z4.w);
            __half2 p01 = __floats2half2_rn(v0, v1);
            __half2 p23 = __floats2half2_rn(v2, v3);
            uint2 st;
            st.x = *reinterpret_cast<uint32_t*>(&p01);
            st.y = *reinterpret_cast<uint32_t*>(&p23);
            *reinterpret_cast<uint2*>(yy16 + row * DI + d0 + c) = st;
        }
        __syncthreads();
    }
    if (ck == NCH - 1)
        *reinterpret_cast<float2*>(&outp[OOUT_SSM + (size_t)ch * NSTATE + sub * 2]) =
            make_float2(h0, h1);
}

// ---------------- launch ----------------------------------------------------
extern "C" void kernel_launch(void* const* d_in, const int* in_sizes, int n_in,
                              void* d_out, int out_size) {
    const float* x         = (const float*)d_in[0];
    const float* ln_w      = (const float*)d_in[1];
    const float* ln_b      = (const float*)d_in[2];
    const float* in_proj_w = (const float*)d_in[3];
    const float* conv_w    = (const float*)d_in[4];
    const float* conv_b    = (const float*)d_in[5];
    const float* x_proj_w  = (const float*)d_in[6];
    const float* dt_proj_w = (const float*)d_in[7];
    const float* dt_proj_b = (const float*)d_in[8];
    const float* A_log     = (const float*)d_in[9];
    const float* D_param   = (const float*)d_in[10];
    const float* out_proj_w= (const float*)d_in[11];
    const float* res_scale = (const float*)d_in[12];
    float* out = (float*)d_out;

    float* S = nullptr;
    cudaGetSymbolAddress((void**)&S, g_scratch);

    float*  z      = S + O_Z;
    float*  xmT    = S + O_XMT;
    float*  xcT    = S + O_XCT;
    float*  dtT    = S + O_DTT;
    float*  xdbl   = S + O_XDBL;
    float*  w_x    = S + O_WX;
    float*  xpart  = S + O_XPART;
    float*  aprod  = S + O_APROD;
    float*  bst    = S + O_BST;
    float*  hin    = S + O_HIN;
    __half* xn16   = (__half*)(S + O_XN16);
    __half* w_in16 = (__half*)(S + O_WIN16);
    __half* w_out16= (__half*)(S + O_WOUT16);
    __half* w_dt16 = (__half*)(S + O_WDT16);
    __half* yy16   = (__half*)(S + O_YY16);
    __half* xdbl16 = (__half*)(S + O_XDBL16);

    const int HSMEM = 61440;   // 3-stage ring
    cudaFuncSetAttribute(hgemm_xz, cudaFuncAttributeMaxDynamicSharedMemorySize, HSMEM);
    cudaFuncSetAttribute(hgemm<2>, cudaFuncAttributeMaxDynamicSharedMemorySize, HSMEM);
    cudaFuncSetAttribute(hgemm<3>, cudaFuncAttributeMaxDynamicSharedMemorySize, HSMEM);

    dim3 tb(32, 8);

    // 1) in_proj_w -> w_in16 [2DI][DM]
    cvtT_half_kernel<<<dim3(2 * DI / 32, DM / 32), tb>>>(in_proj_w, w_in16, DM, 2 * DI);
    // 2) out_proj_w -> w_out16 [DM][DI]
    cvtT_half_kernel<<<dim3(DM / 32, DI / 32), tb>>>(out_proj_w, w_out16, DI, DM);
    // 3) LayerNorm (half output)
    ln_kernel<<<MROWS, 256>>>(x, ln_w, ln_b, xn16);

    // 4) fused x-GEMM + z-GEMM (1024 CTAs)   [profiled slot]
    hgemm_xz<<<1024, 128, HSMEM>>>(xn16, w_in16, xmT, z);

    // 5) dt_proj_w -> w_dt16 [DI][RDT]
    cvtT_half_kernel<<<dim3(DI / 32, RDT / 32), tb>>>(dt_proj_w, w_dt16, RDT, DI);
    // 6) x_proj_w tf32 convert
    cvt_wx_kernel<<<(DI * XPW / 4 + 255) / 256, 256>>>(x_proj_w, w_x, DI * XPW);

    // 7) conv + silu + conv-state ([d][MROWS] layout)
    conv_silu_kernel<<<DI * BBATCH, 256>>>(xmT, xcT, conv_w, conv_b, out);

    // 8) x_proj split-K (tf32) from xcT
    xproj_kernel<<<dim3(MROWS / 128, 4), 256>>>(xcT, w_x, xpart);

    // 9) reduce partials -> xdbl + xdbl16
    xdbl_reduce_kernel<<<(MROWS * XPW / 4 + 255) / 256, 256>>>(xpart, xdbl, xdbl16);

    // 10) dt-GEMM (transposed output + softplus/bias[row]): dtT[d][token]
    hgemm<3><<<dim3(MROWS / 128, DI / 128), 128, HSMEM>>>(
        w_dt16, RDT, xdbl16, RDT, dtT, MROWS,
        DI, MROWS, RDT, dt_proj_b, nullptr, 0, nullptr);

    // 11) chunked scan: phase1 -> phase2 -> phase3 (+gate)
    scan_phase1<<<dim3((BBATCH * DI) / 32, NCH), 256>>>(
        dtT, xcT, xdbl, A_log, aprod, bst);
    scan_phase2<<<(BBATCH * DI * NSTATE + 255) / 256, 256>>>(aprod, bst, hin);
    scan_phase3<<<dim3((BBATCH * DI) / 32, NCH), 256>>>(
        dtT, xcT, xdbl, A_log, hin, D_param, z, yy16, out);

    // 12) out_proj (fp16 HMMA) + residual
    hgemm<2><<<dim3(DM / 128, MROWS / 128), 128, HSMEM>>>(
        yy16, DI, w_out16, DI, out, DM,
        MROWS, DM, DI, nullptr, x, DM, res_scale);
}

// round 16
// speedup vs baseline: 1.0316x; 1.0316x over previous
#include <cuda_runtime.h>
#include <cuda_fp16.h>
#include <math.h>
#include <stdint.h>

// ---------------- problem constants ----------------
#define DM   1024
#define LL   2048
#define BBATCH 2
#define DI   2048
#define NSTATE 16
#define RDT  64
#define XPW  96
#define MROWS (BBATCH*LL)
#define NCH  32
#define CLEN (LL/NCH)

// ---------------- scratch (offsets in floats) ----------------
#define O_Z      ((size_t)0)                           // [MROWS, DI]
#define O_XMT    (O_Z      + (size_t)MROWS*DI)         // [DI, MROWS]
#define O_XCT    (O_XMT    + (size_t)DI*MROWS)         // [DI, MROWS]
#define O_DTT    (O_XCT    + (size_t)DI*MROWS)         // [DI, MROWS]
#define O_XDBL   (O_DTT    + (size_t)DI*MROWS)         // [MROWS, 96]
#define O_WX     (O_XDBL   + (size_t)MROWS*XPW)        // tf32 [DI][96]
#define O_XPART  (O_WX     + (size_t)DI*XPW)           // [4][MROWS][96]
#define O_XN16   (O_XPART  + (size_t)4*MROWS*XPW)      // half [MROWS][DM]
#define O_WIN16  (O_XN16   + (size_t)MROWS*DM/2)       // half [2DI][DM]
#define O_WOUT16 (O_WIN16  + (size_t)DM*2*DI/2)        // half [DM][DI]
#define O_WDT16  (O_WOUT16 + (size_t)DI*DM/2)          // half [DI][RDT]
#define O_YY16   (O_WDT16  + (size_t)DI*RDT/2)         // half [MROWS][DI]
#define O_XDBL16 (O_YY16   + (size_t)MROWS*DI/2)       // half [MROWS][64]
#define O_APROD  (O_XDBL16 + (size_t)MROWS*64/2)
#define O_BST    (O_APROD  + (size_t)BBATCH*DI*NCH*16)
#define O_HIN    (O_BST    + (size_t)BBATCH*DI*NCH*16)
#define O_TOTAL  (O_HIN    + (size_t)BBATCH*DI*NCH*16)

__device__ __align__(16) float g_scratch[O_TOTAL];

#define OOUT_SSM  ((size_t)MROWS*DM)
#define OOUT_CONV (OOUT_SSM + (size_t)BBATCH*DI*NSTATE)

__device__ __forceinline__ float siluf(float v) { return v / (1.0f + __expf(-v)); }

__device__ __forceinline__ uint32_t f2tf(float f) {
    uint32_t u;
    asm("cvt.rna.tf32.f32 %0, %1;" : "=r"(u) : "f"(f));
    return u;
}

#define CP16(saddr, gptr) \
    asm volatile("cp.async.cg.shared.global [%0], [%1], 16;" :: "r"(saddr), "l"(gptr))

__device__ __forceinline__ void ldsm4(uint32_t& r0, uint32_t& r1, uint32_t& r2,
                                      uint32_t& r3, uint32_t addr) {
    asm volatile("ldmatrix.sync.aligned.m8n8.x4.shared.b16 {%0,%1,%2,%3}, [%4];"
                 : "=r"(r0), "=r"(r1), "=r"(r2), "=r"(r3) : "r"(addr));
}

// ================= fp16 HMMA GEMM core (device) ==============================
// 64x64 warp tiles, BM=BN=128, BK=32, 4-stage ring, 1 sync/tile, 128 threads.
template<int EPI>
__device__ __forceinline__ void hgemm_body(
      const __half* __restrict__ A, int lda,
      const __half* __restrict__ Bt, int ldb,
      float* __restrict__ C, int ldc,
      int K, int row0, int col0,
      const float* __restrict__ bias,
      const float* __restrict__ resid, int ldr,
      const float* __restrict__ scale_ptr,
      char* sm) {
    constexpr int ROWB = 80;
    constexpr int TILEB = 128 * ROWB;
    constexpr int STAGEB = 2 * TILEB;

    const int tid  = threadIdx.x;
    const int lane = tid & 31;
    const int wid  = tid >> 5;
    const int wm0 = (wid >> 1) * 64;
    const int wn0 = (wid & 1) * 64;
    const int g = lane >> 2;
    const int t = lane & 3;

    uint32_t sBase = (uint32_t)__cvta_generic_to_shared(sm);

    const int a_row  = wm0 + (lane & 7) + ((lane >> 3) & 1) * 8;
    const int a_coff = ((lane >> 4) & 1) * 16;
    const int b_row  = wn0 + (lane & 7) + ((lane >> 4) & 1) * 8;
    const int b_coff = ((lane >> 3) & 1) * 16;
    const uint32_t aOff = (uint32_t)(a_row * ROWB + a_coff);
    const uint32_t bOff = (uint32_t)(TILEB + b_row * ROWB + b_coff);

    auto issueCopy = [&](int st, int k0) {
        #pragma unroll
        for (int p = 0; p < 4; p++) {
            int e = tid + p * 128;
            int r = e >> 2, c = e & 3;
            uint32_t dst = sBase + (uint32_t)(st * STAGEB + r * ROWB + c * 16);
            CP16(dst, A + (size_t)(row0 + r) * lda + k0 + c * 8);
            CP16(dst + TILEB, Bt + (size_t)(col0 + r) * ldb + k0 + c * 8);
        }
        asm volatile("cp.async.commit_group;");
    };

    float acc[4][8][4];
    #pragma unroll
    for (int mi = 0; mi < 4; mi++)
        #pragma unroll
        for (int ni = 0; ni < 8; ni++)
            #pragma unroll
            for (int e = 0; e < 4; e++) acc[mi][ni][e] = 0.f;

    const int nk = K / 32;
    issueCopy(0, 0);
    if (nk > 1) issueCopy(1, 32);
    if (nk > 2) issueCopy(2, 64);

    for (int kt = 0; kt < nk; kt++) {
        if (kt < nk - 2)
            asm volatile("cp.async.wait_group 2;");
        else if (kt == nk - 2)
            asm volatile("cp.async.wait_group 1;");
        else
            asm volatile("cp.async.wait_group 0;");
        __syncthreads();
        if (kt + 3 < nk) issueCopy((kt + 3) & 3, (kt + 3) * 32);

        uint32_t stBase = sBase + (uint32_t)((kt & 3) * STAGEB);
        #pragma unroll
        for (int ks = 0; ks < 2; ks++) {
            uint32_t af[4][4], bf[8][2];
            #pragma unroll
            for (int mi = 0; mi < 4; mi++)
                ldsm4(af[mi][0], af[mi][1], af[mi][2], af[mi][3],
                      stBase + aOff + mi * (16 * ROWB) + ks * 32);
            #pragma unroll
            for (int nq = 0; nq < 4; nq++)
                ldsm4(bf[2 * nq][0], bf[2 * nq][1], bf[2 * nq + 1][0], bf[2 * nq + 1][1],
                      stBase + bOff + nq * (16 * ROWB) + ks * 32);
            #pragma unroll
            for (int mi = 0; mi < 4; mi++)
                #pragma unroll
                for (int ni = 0; ni < 8; ni++)
                    asm volatile(
                        "mma.sync.aligned.m16n8k16.row.col.f32.f16.f16.f32 "
                        "{%0,%1,%2,%3}, {%4,%5,%6,%7}, {%8,%9}, {%0,%1,%2,%3};"
                        : "+f"(acc[mi][ni][0]), "+f"(acc[mi][ni][1]),
                          "+f"(acc[mi][ni][2]), "+f"(acc[mi][ni][3])
                        : "r"(af[mi][0]), "r"(af[mi][1]),
                          "r"(af[mi][2]), "r"(af[mi][3]),
                          "r"(bf[ni][0]), "r"(bf[ni][1]));
        }
    }

    float scl = (EPI == 2) ? scale_ptr[0] : 1.0f;
    #pragma unroll
    for (int mi = 0; mi < 4; mi++) {
        int r0 = row0 + wm0 + mi * 16 + g;
        #pragma unroll
        for (int ni = 0; ni < 8; ni++) {
            int c0n = col0 + wn0 + ni * 8 + t * 2;
            #pragma unroll
            for (int e = 0; e < 4; e++) {
                int rr = r0 + ((e >= 2) ? 8 : 0);
                int cc = c0n + (e & 1);
                float v = acc[mi][ni][e];
                if (EPI == 1) {
                    v += bias[cc];
                    v = (v > 20.0f) ? v : log1pf(__expf(v));
                } else if (EPI == 2) {
                    v = scl * v + resid[(size_t)rr * ldr + cc];
                } else if (EPI == 3) {
                    v += bias[rr];
                    v = (v > 20.0f) ? v : log1pf(__expf(v));
                }
                C[(size_t)rr * ldc + cc] = v;
            }
        }
    }
}

template<int EPI>
__global__ void __launch_bounds__(128, 2)
hgemm(const __half* __restrict__ A, int lda,
      const __half* __restrict__ Bt, int ldb,
      float* __restrict__ C, int ldc,
      int M, int N, int K,
      const float* __restrict__ bias,
      const float* __restrict__ resid, int ldr,
      const float* __restrict__ scale_ptr) {
    extern __shared__ __align__(16) char sm[];
    hgemm_body<EPI>(A, lda, Bt, ldb, C, ldc, K,
                    blockIdx.y * 128, blockIdx.x * 128,
                    bias, resid, ldr, scale_ptr, sm);
}

// fused x-GEMM + z-GEMM: 1024 blocks.
__global__ void __launch_bounds__(128, 2)
hgemm_xz(const __half* __restrict__ xn16,
         const __half* __restrict__ w_in16,
         float* __restrict__ xmT, float* __restrict__ z) {
    extern __shared__ __align__(16) char sm[];
    int bid = blockIdx.x;
    if (bid < 512) {
        int bx = bid & 31, by = bid >> 5;
        hgemm_body<0>(w_in16, DM, xn16, DM, xmT, MROWS, DM,
                      by * 128, bx * 128, nullptr, nullptr, 0, nullptr, sm);
    } else {
        bid -= 512;
        int bx = bid & 15, by = bid >> 4;
        hgemm_body<0>(xn16, DM, w_in16 + (size_t)DI * DM, DM, z, DI, DM,
                      by * 128, bx * 128, nullptr, nullptr, 0, nullptr, sm);
    }
}

// ---------------- weight convert+transpose to half --------------------------
__global__ void cvtT_half_kernel(const float* __restrict__ in, __half* __restrict__ out,
                                 int R, int C) {
    __shared__ float tile[32][33];
    int c0 = blockIdx.x * 32, r0 = blockIdx.y * 32;
    #pragma unroll
    for (int j = 0; j < 32; j += 8)
        tile[threadIdx.y + j][threadIdx.x] =
            in[(size_t)(r0 + threadIdx.y + j) * C + c0 + threadIdx.x];
    __syncthreads();
    #pragma unroll
    for (int j = 0; j < 32; j += 8)
        out[(size_t)(c0 + threadIdx.y + j) * R + r0 + threadIdx.x] =
            __float2half_rn(tile[threadIdx.x][threadIdx.y + j]);
}

// ---------------- tf32 convert (x_proj weight) -------------------------------
__global__ void cvt_wx_kernel(const float* __restrict__ s, float* __restrict__ d, int n) {
    int i = (blockIdx.x * 256 + threadIdx.x) * 4;
    if (i < n) {
        float4 v = *reinterpret_cast<const float4*>(s + i);
        uint4 u = make_uint4(f2tf(v.x), f2tf(v.y), f2tf(v.z), f2tf(v.w));
        *reinterpret_cast<uint4*>(d + i) = u;
    }
}

// ---------------- LayerNorm (emits half) -------------------------------------
__global__ void ln_kernel(const float* __restrict__ x,
                          const float* __restrict__ w,
                          const float* __restrict__ b,
                          __half* __restrict__ xn16) {
    int row = blockIdx.x;
    const float4* px = reinterpret_cast<const float4*>(x + (size_t)row * DM);
    float4 v = px[threadIdx.x];
    float s  = v.x + v.y + v.z + v.w;
    float sq = v.x*v.x + v.y*v.y + v.z*v.z + v.w*v.w;
    #pragma unroll
    for (int o = 16; o; o >>= 1) {
        s  += __shfl_xor_sync(0xffffffffu, s,  o);
        sq += __shfl_xor_sync(0xffffffffu, sq, o);
    }
    __shared__ float ss[8], sqs[8];
    __shared__ float s_mu, s_rs;
    int wid = threadIdx.x >> 5, lid = threadIdx.x & 31;
    if (lid == 0) { ss[wid] = s; sqs[wid] = sq; }
    __syncthreads();
    if (threadIdx.x == 0) {
        float S = 0.f, Q = 0.f;
        #pragma unroll
        for (int i = 0; i < 8; i++) { S += ss[i]; Q += sqs[i]; }
        float m = S * (1.0f / DM);
        float var = Q * (1.0f / DM) - m * m;
        s_mu = m;
        s_rs = rsqrtf(var + 1e-5f);
    }
    __syncthreads();
    float m = s_mu, r = s_rs;
    float4 wv = reinterpret_cast<const float4*>(w)[threadIdx.x];
    float4 bv = reinterpret_cast<const float4*>(b)[threadIdx.x];
    __half2 h01 = __floats2half2_rn((v.x - m) * r * wv.x + bv.x,
                                    (v.y - m) * r * wv.y + bv.y);
    __half2 h23 = __floats2half2_rn((v.z - m) * r * wv.z + bv.z,
                                    (v.w - m) * r * wv.w + bv.w);
    uint2 st;
    st.x = *reinterpret_cast<uint32_t*>(&h01);
    st.y = *reinterpret_cast<uint32_t*>(&h23);
    *reinterpret_cast<uint2*>(xn16 + (size_t)row * DM + threadIdx.x * 4) = st;
}

// ---------------- x_proj split-K kernel (tf32, reads xcT [d][MROWS]) ---------
__global__ void __launch_bounds__(256, 2)
xproj_kernel(const float* __restrict__ xcT,
             const float* __restrict__ Wx,
             float* __restrict__ part) {
    constexpr int BK = 16, SAT = 136, SBX = 104;
    constexpr int ASZ = BK * SAT, BSZ = BK * SBX;
    __shared__ float At[3 * ASZ];
    __shared__ float Bt[3 * BSZ];

    const int tid  = threadIdx.x;
    const int lane = tid & 31;
    const int wid  = tid >> 5;
    const int wm0 = (wid >> 2) * 64;
    const int wn0 = (wid & 3) * 24;
    const int g = lane >> 2, t = lane & 3;

    const int tok0 = blockIdx.x * 128;
    const int kbase = blockIdx.y * (DI / 4);

    uint32_t aSm = (uint32_t)__cvta_generic_to_shared(At);
    uint32_t bSm = (uint32_t)__cvta_generic_to_shared(Bt);

    auto issueCopy = [&](int st, int k0) {
        int kg = kbase + k0;
        #pragma unroll
        for (int p = 0; p < 2; p++) {
            int idx = tid + p * 256;
            int r = idx >> 5, c = idx & 31;
            CP16(aSm + (uint32_t)(st * ASZ + r * SAT + c * 4) * 4,
                 xcT + (size_t)(kg + r) * MROWS + tok0 + c * 4);
        }
        #pragma unroll
        for (int p = 0; p < 2; p++) {
            int idx = tid + p * 256;
            if (idx < 384) {
                int r = idx / 24, c = idx % 24;
                CP16(bSm + (uint32_t)(st * BSZ + r * SBX + c * 4) * 4,
                     Wx + (size_t)(kg + r) * XPW + c * 4);
            }
        }
        asm volatile("cp.async.commit_group;");
    };

    float acc[4][3][4];
    #pragma unroll
    for (int mi = 0; mi < 4; mi++)
        #pragma unroll
        for (int ni = 0; ni < 3; ni++)
            #pragma unroll
            for (int e = 0; e < 4; e++) acc[mi][ni][e] = 0.f;

    const int nk = (DI / 4) / BK;
    issueCopy(0, 0);
    issueCopy(1, BK);

    for (int kt = 0; kt < nk; kt++) {
        if (kt + 1 < nk)
            asm volatile("cp.async.wait_group 1;");
        else
            asm volatile("cp.async.wait_group 0;");
        __syncthreads();
        if (kt + 2 < nk) issueCopy((kt + 2) % 3, (kt + 2) * BK);

        const float* Af = At + (kt % 3) * ASZ;
        const float* Bf = Bt + (kt % 3) * BSZ;
        #pragma unroll
        for (int ks = 0; ks < 2; ks++) {
            uint32_t af[4][4], bf[3][2];
            #pragma unroll
            for (int mi = 0; mi < 4; mi++) {
                const float* pa = Af + (ks * 8 + t) * SAT + wm0 + mi * 16 + g;
                af[mi][0] = f2tf(pa[0]);
                af[mi][1] = f2tf(pa[8]);
                af[mi][2] = f2tf(pa[4 * SAT]);
                af[mi][3] = f2tf(pa[4 * SAT + 8]);
            }
            #pragma unroll
            for (int ni = 0; ni < 3; ni++) {
                const float* pb = Bf + (ks * 8 + t) * SBX + wn0 + ni * 8 + g;
                bf[ni][0] = __float_as_uint(pb[0]);
                bf[ni][1] = __float_as_uint(pb[4 * SBX]);
            }
            #pragma unroll
            for (int mi = 0; mi < 4; mi++)
                #pragma unroll
                for (int ni = 0; ni < 3; ni++)
                    asm volatile(
                        "mma.sync.aligned.m16n8k8.row.col.f32.tf32.tf32.f32 "
                        "{%0,%1,%2,%3}, {%4,%5,%6,%7}, {%8,%9}, {%0,%1,%2,%3};"
                        : "+f"(acc[mi][ni][0]), "+f"(acc[mi][ni][1]),
                          "+f"(acc[mi][ni][2]), "+f"(acc[mi][ni][3])
                        : "r"(af[mi][0]), "r"(af[mi][1]),
                          "r"(af[mi][2]), "r"(af[mi][3]),
                          "r"(bf[ni][0]), "r"(bf[ni][1]));
        }
        __syncthreads();
    }

    float* po = part + (size_t)blockIdx.y * MROWS * XPW;
    #pragma unroll
    for (int mi = 0; mi < 4; mi++) {
        int r0 = tok0 + wm0 + mi * 16 + g;
        #pragma unroll
        for (int ni = 0; ni < 3; ni++) {
            int c0n = wn0 + ni * 8 + t * 2;
            #pragma unroll
            for (int e = 0; e < 4; e++) {
                int rr = r0 + ((e >= 2) ? 8 : 0);
                int cc = c0n + (e & 1);
                po[(size_t)rr * XPW + cc] = acc[mi][ni][e];
            }
        }
    }
}

// ---------------- reduce 4 x_proj partials -----------------------------------
__global__ void xdbl_reduce_kernel(const float* __restrict__ part,
                                   float* __restrict__ xdbl,
                                   __half* __restrict__ xdbl16) {
    constexpr size_t N4 = (size_t)MROWS * XPW / 4;
    size_t i = (size_t)blockIdx.x * 256 + threadIdx.x;
    if (i < N4) {
        const float4* p = reinterpret_cast<const float4*>(part);
        float4 a = p[i], b = p[i + N4], c = p[i + 2 * N4], d = p[i + 3 * N4];
        float4 r = make_float4(a.x + b.x + c.x + d.x, a.y + b.y + c.y + d.y,
                               a.z + b.z + c.z + d.z, a.w + b.w + c.w + d.w);
        reinterpret_cast<float4*>(xdbl)[i] = r;
        size_t row = (i * 4) / XPW;
        int col = (int)((i * 4) % XPW);
        if (col < RDT) {
            __half2 h01 = __floats2half2_rn(r.x, r.y);
            __half2 h23 = __floats2half2_rn(r.z, r.w);
            uint2 st;
            st.x = *reinterpret_cast<uint32_t*>(&h01);
            st.y = *reinterpret_cast<uint32_t*>(&h23);
            *reinterpret_cast<uint2*>(xdbl16 + row * RDT + col) = st;
        }
    }
}

// ---------------- depthwise causal conv (float4), [d][MROWS] layout ----------
__global__ void conv_silu_kernel(const float* __restrict__ in,
                                 float* __restrict__ out,
                                 const float* __restrict__ cw,
                                 const float* __restrict__ cb,
                                 float* __restrict__ outp) {
    int chb = blockIdx.x;
    int d  = chb / BBATCH;
    int b  = chb % BBATCH;
    const float* pin = in + (size_t)d * MROWS + b * LL;
    float* pout = out + (size_t)d * MROWS + b * LL;
    float w0 = cw[d * 4 + 0], w1 = cw[d * 4 + 1], w2 = cw[d * 4 + 2], w3 = cw[d * 4 + 3];
    float bias = cb[d];
    for (int base = threadIdx.x * 4; base < LL; base += blockDim.x * 4) {
        float4 cur = *reinterpret_cast<const float4*>(pin + base);
        float4 prev = (base >= 4) ? *reinterpret_cast<const float4*>(pin + base - 4)
                                  : make_float4(0.f, 0.f, 0.f, 0.f);
        float o0 = bias + w0 * prev.y + w1 * prev.z + w2 * prev.w + w3 * cur.x;
        float o1 = bias + w0 * prev.z + w1 * prev.w + w2 * cur.x + w3 * cur.y;
        float o2 = bias + w0 * prev.w + w1 * cur.x + w2 * cur.y + w3 * cur.z;
        float o3 = bias + w0 * cur.x  + w1 * cur.y + w2 * cur.z + w3 * cur.w;
        *reinterpret_cast<float4*>(pout + base) =
            make_float4(siluf(o0), siluf(o1), siluf(o2), siluf(o3));
    }
    if (threadIdx.x < 3)
        outp[OOUT_CONV + ((size_t)b * DI + d) * 3 + threadIdx.x] = pin[LL - 3 + threadIdx.x];
}

// ---------------- chunked scan common helpers -------------------------------
struct ScanCtx {
    float A0, A1;
    bool fastok;
    bool b1, b2, b4;
};

__device__ __forceinline__ ScanCtx scan_ctx(const float* A_log, int d, int sub) {
    ScanCtx c;
    float2 Al = *reinterpret_cast<const float2*>(&A_log[d * NSTATE + sub * 2]);
    float a0e = __expf(Al.x);
    float a1e = __expf(Al.y);
    c.A0 = -a0e; c.A1 = -a1e;
    float fi0 = (float)(2 * sub + 1);
    bool ok = (fabsf(a0e - fi0) < 1e-4f) && (fabsf(a1e - (fi0 + 1.0f)) < 1e-4f);
    c.fastok = __all_sync(0xffffffffu, ok);
    c.b1 = (sub & 1); c.b2 = (sub & 2); c.b4 = (sub & 4);
    return c;
}

__device__ __forceinline__ void scan_da(const ScanCtx& c, float dt,
                                        float& da0, float& da1) {
    if (c.fastok) {
        float E  = __expf(-dt);
        float E2 = E * E;
        float E4 = E2 * E2;
        float E8 = E4 * E4;
        float q = E;
        if (c.b1) q *= E2;
        if (c.b2) q *= E4;
        if (c.b4) q *= E8;
        da0 = q;
        da1 = q * E;
    } else {
        da0 = __expf(c.A0 * dt);
        da1 = __expf(c.A1 * dt);
    }
}

// ---------------- scan phase 1 ------------------------------------------------
__global__ void __launch_bounds__(256)
scan_phase1(const float* __restrict__ dtT, const float* __restrict__ xT,
            const float* __restrict__ xdbl, const float* __restrict__ A_log,
            float* __restrict__ aprod, float* __restrict__ bst) {
    int tid = threadIdx.x;
    int ch  = blockIdx.x * 32 + (tid >> 3);
    int sub = tid & 7;
    int ck  = blockIdx.y;
    int b   = ch / DI;
    int d   = ch & (DI - 1);
    ScanCtx cx = scan_ctx(A_log, d, sub);

    const float* pdt = dtT + (size_t)d * MROWS + b * LL + ck * CLEN;
    const float* px  = xT  + (size_t)d * MROWS + b * LL + ck * CLEN;
    const float* pbc = xdbl + ((size_t)b * LL + ck * CLEN) * XPW;

    float h0 = 0.f, h1 = 0.f, ap0 = 1.f, ap1 = 1.f;
    for (int t0 = 0; t0 < CLEN; t0 += 8) {
        float4 dtA = *reinterpret_cast<const float4*>(pdt + t0);
        float4 dtB = *reinterpret_cast<const float4*>(pdt + t0 + 4);
        float4 xvA = *reinterpret_cast<const float4*>(px + t0);
        float4 xvB = *reinterpret_cast<const float4*>(px + t0 + 4);
        float dts[8] = {dtA.x, dtA.y, dtA.z, dtA.w, dtB.x, dtB.y, dtB.z, dtB.w};
        float xvs[8] = {xvA.x, xvA.y, xvA.z, xvA.w, xvB.x, xvB.y, xvB.z, xvB.w};
        #pragma unroll
        for (int j = 0; j < 8; j++) {
            float dt = dts[j];
            const float* prow = pbc + (size_t)(t0 + j) * XPW;
            float2 Bv = *reinterpret_cast<const float2*>(prow + RDT + sub * 2);
            float da0, da1;
            scan_da(cx, dt, da0, da1);
            float dx = dt * xvs[j];
            h0 = fmaf(da0, h0, Bv.x * dx);
            h1 = fmaf(da1, h1, Bv.y * dx);
            ap0 *= da0;
            ap1 *= da1;
        }
    }
    size_t o = ((size_t)ch * NCH + ck) * NSTATE + sub * 2;
    *reinterpret_cast<float2*>(bst + o)   = make_float2(h0, h1);
    *reinterpret_cast<float2*>(aprod + o) = make_float2(ap0, ap1);
}

// ---------------- scan phase 2 ------------------------------------------------
__global__ void scan_phase2(const float* __restrict__ aprod,
                            const float* __restrict__ bst,
                            float* __restrict__ hin) {
    int idx = blockIdx.x * 256 + threadIdx.x;
    if (idx < BBATCH * DI * NSTATE) {
        int ch = idx >> 4;
        int n  = idx & 15;
        float h = 0.f;
        #pragma unroll
        for (int c = 0; c < NCH; c++) {
            size_t o = ((size_t)ch * NCH + c) * NSTATE + n;
            hin[o] = h;
            h = fmaf(aprod[o], h, bst[o]);
        }
    }
}

// ---------------- scan phase 3: seeded scan + fused gate ----------------------
__global__ void __launch_bounds__(256)
scan_phase3(const float* __restrict__ dtT, const float* __restrict__ xT,
            const float* __restrict__ xdbl, const float* __restrict__ A_log,
            const float* __restrict__ hin, const float* __restrict__ Dp,
            const float* __restrict__ z,
            __half* __restrict__ yy16, float* __restrict__ outp) {
    __shared__ float ysm[32][33];
    __shared__ float xsm[32][33];
    __shared__ float dsm[32];

    int tid = threadIdx.x;
    int cl  = tid >> 3;
    int sub = tid & 7;
    int ck  = blockIdx.y;
    int chBase = blockIdx.x * 32;
    int ch  = chBase + cl;
    int b   = ch / DI;
    int d   = ch & (DI - 1);
    int d0  = chBase & (DI - 1);
    ScanCtx cx = scan_ctx(A_log, d, sub);

    if (tid < 32) dsm[tid] = Dp[d0 + tid];

    const float* pdt = dtT + (size_t)d * MROWS + b * LL + ck * CLEN;
    const float* px  = xT  + (size_t)d * MROWS + b * LL + ck * CLEN;
    const float* pbc = xdbl + ((size_t)b * LL + ck * CLEN) * XPW;

    float2 h = *reinterpret_cast<const float2*>(
        hin + ((size_t)ch * NCH + ck) * NSTATE + sub * 2);
    float h0 = h.x, h1 = h.y;
    __syncthreads();

    for (int tb = 0; tb < CLEN; tb += 32) {
        #pragma unroll
        for (int g8 = 0; g8 < 4; g8++) {
            int t0 = tb + g8 * 8;
            float4 dtA = *reinterpret_cast<const float4*>(pdt + t0);
            float4 dtB = *reinterpret_cast<const float4*>(pdt + t0 + 4);
            float4 xvA = *reinterpret_cast<const float4*>(px + t0);
            float4 xvB = *reinterpret_cast<const float4*>(px + t0 + 4);
            float dts[8] = {dtA.x, dtA.y, dtA.z, dtA.w, dtB.x, dtB.y, dtB.z, dtB.w};
            float xvs[8] = {xvA.x, xvA.y, xvA.z, xvA.w, xvB.x, xvB.y, xvB.z, xvB.w};
            float pj[8];
            #pragma unroll
            for (int j = 0; j < 8; j++) {
                float dt = dts[j];
                const float* prow = pbc + (size_t)(t0 + j) * XPW;
                float2 Bv = *reinterpret_cast<const float2*>(prow + RDT + sub * 2);
                float2 Cv = *reinterpret_cast<const float2*>(prow + RDT + NSTATE + sub * 2);
                float da0, da1;
                scan_da(cx, dt, da0, da1);
                float dx = dt * xvs[j];
                h0 = fmaf(da0, h0, Bv.x * dx);
                h1 = fmaf(da1, h1, Bv.y * dx);
                pj[j] = fmaf(h0, Cv.x, h1 * Cv.y);
            }
            #pragma unroll
            for (int off = 4; off; off >>= 1)
                #pragma unroll
                for (int j = 0; j < 8; j++)
                    pj[j] += __shfl_xor_sync(0xffffffffu, pj[j], off, 8);
            if (sub == 0) {
                int r = g8 * 8;
                #pragma unroll
                for (int j = 0; j < 8; j++) {
                    ysm[r + j][cl] = pj[j];
                    xsm[r + j][cl] = xvs[j];
                }
            }
        }
        __syncthreads();
        {
            int r = tid >> 3;
            int c = (tid & 7) * 4;
            size_t row = (size_t)b * LL + ck * CLEN + tb + r;
            float4 z4 = *reinterpret_cast<const float4*>(z + row * DI + d0 + c);
            float v0 = (ysm[r][c + 0] + xsm[r][c + 0] * dsm[c + 0]) * siluf(z4.x);
            float v1 = (ysm[r][c + 1] + xsm[r][c + 1] * dsm[c + 1]) * siluf(z4.y);
            float v2 = (ysm[r][c + 2] + xsm[r][c + 2] * dsm[c + 2]) * siluf(z4.z);
            float v3 = (ysm[r][c + 3] + xsm[r][c + 3] * dsm[c + 3]) * siluf(z4.w);
            __half2 p01 = __floats2half2_rn(v0, v1);
            __half2 p23 = __floats2half2_rn(v2, v3);
            uint2 st;
            st.x = *reinterpret_cast<uint32_t*>(&p01);
            st.y = *reinterpret_cast<uint32_t*>(&p23);
            *reinterpret_cast<uint2*>(yy16 + row * DI + d0 + c) = st;
        }
        __syncthreads();
    }
    if (ck == NCH - 1)
        *reinterpret_cast<float2*>(&outp[OOUT_SSM + (size_t)ch * NSTATE + sub * 2]) =
            make_float2(h0, h1);
}

// ---------------- launch ----------------------------------------------------
extern "C" void kernel_launch(void* const* d_in, const int* in_sizes, int n_in,
                              void* d_out, int out_size) {
    const float* x         = (const float*)d_in[0];
    const float* ln_w      = (const float*)d_in[1];
    const float* ln_b      = (const float*)d_in[2];
    const float* in_proj_w = (const float*)d_in[3];
    const float* conv_w    = (const float*)d_in[4];
    const float* conv_b    = (const float*)d_in[5];
    const float* x_proj_w  = (const float*)d_in[6];
    const float* dt_proj_w = (const float*)d_in[7];
    const float* dt_proj_b = (const float*)d_in[8];
    const float* A_log     = (const float*)d_in[9];
    const float* D_param   = (const float*)d_in[10];
    const float* out_proj_w= (const float*)d_in[11];
    const float* res_scale = (const float*)d_in[12];
    float* out = (float*)d_out;

    float* S = nullptr;
    cudaGetSymbolAddress((void**)&S, g_scratch);

    float*  z      = S + O_Z;
    float*  xmT    = S + O_XMT;
    float*  xcT    = S + O_XCT;
    float*  dtT    = S + O_DTT;
    float*  xdbl   = S + O_XDBL;
    float*  w_x    = S + O_WX;
    float*  xpart  = S + O_XPART;
    float*  aprod  = S + O_APROD;
    float*  bst    = S + O_BST;
    float*  hin    = S + O_HIN;
    __half* xn16   = (__half*)(S + O_XN16);
    __half* w_in16 = (__half*)(S + O_WIN16);
    __half* w_out16= (__half*)(S + O_WOUT16);
    __half* w_dt16 = (__half*)(S + O_WDT16);
    __half* yy16   = (__half*)(S + O_YY16);
    __half* xdbl16 = (__half*)(S + O_XDBL16);

    const int HSMEM = 81920;   // 4-stage ring
    cudaFuncSetAttribute(hgemm_xz, cudaFuncAttributeMaxDynamicSharedMemorySize, HSMEM);
    cudaFuncSetAttribute(hgemm<2>, cudaFuncAttributeMaxDynamicSharedMemorySize, HSMEM);
    cudaFuncSetAttribute(hgemm<3>, cudaFuncAttributeMaxDynamicSharedMemorySize, HSMEM);

    dim3 tb(32, 8);

    // 1) in_proj_w -> w_in16 [2DI][DM]
    cvtT_half_kernel<<<dim3(2 * DI / 32, DM / 32), tb>>>(in_proj_w, w_in16, DM, 2 * DI);
    // 2) out_proj_w -> w_out16 [DM][DI]
    cvtT_half_kernel<<<dim3(DM / 32, DI / 32), tb>>>(out_proj_w, w_out16, DI, DM);
    // 3) LayerNorm (half output)
    ln_kernel<<<MROWS, 256>>>(x, ln_w, ln_b, xn16);

    // 4) fused x-GEMM + z-GEMM (1024 CTAs, 2 CTA/SM, no spill)  [profiled slot]
    hgemm_xz<<<1024, 128, HSMEM>>>(xn16, w_in16, xmT, z);

    // 5) dt_proj_w -> w_dt16 [DI][RDT]
    cvtT_half_kernel<<<dim3(DI / 32, RDT / 32), tb>>>(dt_proj_w, w_dt16, RDT, DI);
    // 6) x_proj_w tf32 convert
    cvt_wx_kernel<<<(DI * XPW / 4 + 255) / 256, 256>>>(x_proj_w, w_x, DI * XPW);

    // 7) conv + silu + conv-state ([d][MROWS] layout)
    conv_silu_kernel<<<DI * BBATCH, 256>>>(xmT, xcT, conv_w, conv_b, out);

    // 8) x_proj split-K (tf32) from xcT
    xproj_kernel<<<dim3(MROWS / 128, 4), 256>>>(xcT, w_x, xpart);

    // 9) reduce partials -> xdbl + xdbl16
    xdbl_reduce_kernel<<<(MROWS * XPW / 4 + 255) / 256, 256>>>(xpart, xdbl, xdbl16);

    // 10) dt-GEMM (transposed output + softplus/bias[row]): dtT[d][token]
    hgemm<3><<<dim3(MROWS / 128, DI / 128), 128, HSMEM>>>(
        w_dt16, RDT, xdbl16, RDT, dtT, MROWS,
        DI, MROWS, RDT, dt_proj_b, nullptr, 0, nullptr);

    // 11) chunked scan: phase1 -> phase2 -> phase3 (+gate)
    scan_phase1<<<dim3((BBATCH * DI) / 32, NCH), 256>>>(
        dtT, xcT, xdbl, A_log, aprod, bst);
    scan_phase2<<<(BBATCH * DI * NSTATE + 255) / 256, 256>>>(aprod, bst, hin);
    scan_phase3<<<dim3((BBATCH * DI) / 32, NCH), 256>>>(
        dtT, xcT, xdbl, A_log, hin, D_param, z, yy16, out);

    // 12) out_proj (fp16 HMMA) + residual
    hgemm<2><<<dim3(DM / 128, MROWS / 128), 128, HSMEM>>>(
        yy16, DI, w_out16, DI, out, DM,
        MROWS, DM, DI, nullptr, x, DM, res_scale);
}

// round 17
// speedup vs baseline: 1.0378x; 1.0060x over previous
#include <cuda_runtime.h>
#include <cuda_fp16.h>
#include <math.h>
#include <stdint.h>

// ---------------- problem constants ----------------
#define DM   1024
#define LL   2048
#define BBATCH 2
#define DI   2048
#define NSTATE 16
#define RDT  64
#define XPW  96
#define MROWS (BBATCH*LL)
#define NCH  32
#define CLEN (LL/NCH)

// ---------------- scratch (offsets in floats) ----------------
#define O_Z      ((size_t)0)                           // [MROWS, DI]
#define O_XMT    (O_Z      + (size_t)MROWS*DI)         // [DI, MROWS]
#define O_XCT    (O_XMT    + (size_t)DI*MROWS)         // [DI, MROWS] (tf32-rounded)
#define O_DTT    (O_XCT    + (size_t)DI*MROWS)         // [DI, MROWS]
#define O_XDBL   (O_DTT    + (size_t)DI*MROWS)         // [MROWS, 96]
#define O_WX     (O_XDBL   + (size_t)MROWS*XPW)        // tf32 [DI][96]
#define O_XPART  (O_WX     + (size_t)DI*XPW)           // [4][MROWS][96]
#define O_XN16   (O_XPART  + (size_t)4*MROWS*XPW)      // half [MROWS][DM]
#define O_WIN16  (O_XN16   + (size_t)MROWS*DM/2)       // half [2DI][DM]
#define O_WOUT16 (O_WIN16  + (size_t)DM*2*DI/2)        // half [DM][DI]
#define O_WDT16  (O_WOUT16 + (size_t)DI*DM/2)          // half [DI][RDT]
#define O_YY16   (O_WDT16  + (size_t)DI*RDT/2)         // half [MROWS][DI]
#define O_XDBL16 (O_YY16   + (size_t)MROWS*DI/2)       // half [MROWS][64]
#define O_APROD  (O_XDBL16 + (size_t)MROWS*64/2)
#define O_BST    (O_APROD  + (size_t)BBATCH*DI*NCH*16)
#define O_HIN    (O_BST    + (size_t)BBATCH*DI*NCH*16)
#define O_TOTAL  (O_HIN    + (size_t)BBATCH*DI*NCH*16)

__device__ __align__(16) float g_scratch[O_TOTAL];

#define OOUT_SSM  ((size_t)MROWS*DM)
#define OOUT_CONV (OOUT_SSM + (size_t)BBATCH*DI*NSTATE)

__device__ __forceinline__ float siluf(float v) { return v / (1.0f + __expf(-v)); }

__device__ __forceinline__ uint32_t f2tf(float f) {
    uint32_t u;
    asm("cvt.rna.tf32.f32 %0, %1;" : "=r"(u) : "f"(f));
    return u;
}

#define CP16(saddr, gptr) \
    asm volatile("cp.async.cg.shared.global [%0], [%1], 16;" :: "r"(saddr), "l"(gptr))

__device__ __forceinline__ void ldsm4(uint32_t& r0, uint32_t& r1, uint32_t& r2,
                                      uint32_t& r3, uint32_t addr) {
    asm volatile("ldmatrix.sync.aligned.m8n8.x4.shared.b16 {%0,%1,%2,%3}, [%4];"
                 : "=r"(r0), "=r"(r1), "=r"(r2), "=r"(r3) : "r"(addr));
}

// ================= fp16 HMMA GEMM core (device) ==============================
template<int EPI>
__device__ __forceinline__ void hgemm_body(
      const __half* __restrict__ A, int lda,
      const __half* __restrict__ Bt, int ldb,
      float* __restrict__ C, int ldc,
      int K, int row0, int col0,
      const float* __restrict__ bias,
      const float* __restrict__ resid, int ldr,
      const float* __restrict__ scale_ptr,
      char* sm) {
    constexpr int ROWB = 80;
    constexpr int TILEB = 128 * ROWB;
    constexpr int STAGEB = 2 * TILEB;

    const int tid  = threadIdx.x;
    const int lane = tid & 31;
    const int wid  = tid >> 5;
    const int wm0 = (wid >> 1) * 64;
    const int wn0 = (wid & 1) * 64;
    const int g = lane >> 2;
    const int t = lane & 3;

    uint32_t sBase = (uint32_t)__cvta_generic_to_shared(sm);

    const int a_row  = wm0 + (lane & 7) + ((lane >> 3) & 1) * 8;
    const int a_coff = ((lane >> 4) & 1) * 16;
    const int b_row  = wn0 + (lane & 7) + ((lane >> 4) & 1) * 8;
    const int b_coff = ((lane >> 3) & 1) * 16;
    const uint32_t aOff = (uint32_t)(a_row * ROWB + a_coff);
    const uint32_t bOff = (uint32_t)(TILEB + b_row * ROWB + b_coff);

    auto issueCopy = [&](int st, int k0) {
        #pragma unroll
        for (int p = 0; p < 4; p++) {
            int e = tid + p * 128;
            int r = e >> 2, c = e & 3;
            uint32_t dst = sBase + (uint32_t)(st * STAGEB + r * ROWB + c * 16);
            CP16(dst, A + (size_t)(row0 + r) * lda + k0 + c * 8);
            CP16(dst + TILEB, Bt + (size_t)(col0 + r) * ldb + k0 + c * 8);
        }
        asm volatile("cp.async.commit_group;");
    };

    float acc[4][8][4];
    #pragma unroll
    for (int mi = 0; mi < 4; mi++)
        #pragma unroll
        for (int ni = 0; ni < 8; ni++)
            #pragma unroll
            for (int e = 0; e < 4; e++) acc[mi][ni][e] = 0.f;

    const int nk = K / 32;
    issueCopy(0, 0);
    if (nk > 1) issueCopy(1, 32);
    if (nk > 2) issueCopy(2, 64);

    for (int kt = 0; kt < nk; kt++) {
        if (kt < nk - 2)
            asm volatile("cp.async.wait_group 2;");
        else if (kt == nk - 2)
            asm volatile("cp.async.wait_group 1;");
        else
            asm volatile("cp.async.wait_group 0;");
        __syncthreads();
        if (kt + 3 < nk) issueCopy((kt + 3) & 3, (kt + 3) * 32);

        uint32_t stBase = sBase + (uint32_t)((kt & 3) * STAGEB);
        #pragma unroll
        for (int ks = 0; ks < 2; ks++) {
            uint32_t af[4][4], bf[8][2];
            #pragma unroll
            for (int mi = 0; mi < 4; mi++)
                ldsm4(af[mi][0], af[mi][1], af[mi][2], af[mi][3],
                      stBase + aOff + mi * (16 * ROWB) + ks * 32);
            #pragma unroll
            for (int nq = 0; nq < 4; nq++)
                ldsm4(bf[2 * nq][0], bf[2 * nq][1], bf[2 * nq + 1][0], bf[2 * nq + 1][1],
                      stBase + bOff + nq * (16 * ROWB) + ks * 32);
            #pragma unroll
            for (int mi = 0; mi < 4; mi++)
                #pragma unroll
                for (int ni = 0; ni < 8; ni++)
                    asm volatile(
                        "mma.sync.aligned.m16n8k16.row.col.f32.f16.f16.f32 "
                        "{%0,%1,%2,%3}, {%4,%5,%6,%7}, {%8,%9}, {%0,%1,%2,%3};"
                        : "+f"(acc[mi][ni][0]), "+f"(acc[mi][ni][1]),
                          "+f"(acc[mi][ni][2]), "+f"(acc[mi][ni][3])
                        : "r"(af[mi][0]), "r"(af[mi][1]),
                          "r"(af[mi][2]), "r"(af[mi][3]),
                          "r"(bf[ni][0]), "r"(bf[ni][1]));
        }
    }

    float scl = (EPI == 2) ? scale_ptr[0] : 1.0f;
    #pragma unroll
    for (int mi = 0; mi < 4; mi++) {
        int r0 = row0 + wm0 + mi * 16 + g;
        #pragma unroll
        for (int ni = 0; ni < 8; ni++) {
            int c0n = col0 + wn0 + ni * 8 + t * 2;
            #pragma unroll
            for (int e = 0; e < 4; e++) {
                int rr = r0 + ((e >= 2) ? 8 : 0);
                int cc = c0n + (e & 1);
                float v = acc[mi][ni][e];
                if (EPI == 1) {
                    v += bias[cc];
                    v = (v > 20.0f) ? v : log1pf(__expf(v));
                } else if (EPI == 2) {
                    v = scl * v + resid[(size_t)rr * ldr + cc];
                } else if (EPI == 3) {
                    v += bias[rr];
                    v = (v > 20.0f) ? v : log1pf(__expf(v));
                }
                C[(size_t)rr * ldc + cc] = v;
            }
        }
    }
}

template<int EPI>
__global__ void __launch_bounds__(128, 2)
hgemm(const __half* __restrict__ A, int lda,
      const __half* __restrict__ Bt, int ldb,
      float* __restrict__ C, int ldc,
      int M, int N, int K,
      const float* __restrict__ bias,
      const float* __restrict__ resid, int ldr,
      const float* __restrict__ scale_ptr) {
    extern __shared__ __align__(16) char sm[];
    hgemm_body<EPI>(A, lda, Bt, ldb, C, ldc, K,
                    blockIdx.y * 128, blockIdx.x * 128,
                    bias, resid, ldr, scale_ptr, sm);
}

// fused x-GEMM + z-GEMM: 1024 blocks.
__global__ void __launch_bounds__(128, 2)
hgemm_xz(const __half* __restrict__ xn16,
         const __half* __restrict__ w_in16,
         float* __restrict__ xmT, float* __restrict__ z) {
    extern __shared__ __align__(16) char sm[];
    int bid = blockIdx.x;
    if (bid < 512) {
        int bx = bid & 31, by = bid >> 5;
        hgemm_body<0>(w_in16, DM, xn16, DM, xmT, MROWS, DM,
                      by * 128, bx * 128, nullptr, nullptr, 0, nullptr, sm);
    } else {
        bid -= 512;
        int bx = bid & 15, by = bid >> 4;
        hgemm_body<0>(xn16, DM, w_in16 + (size_t)DI * DM, DM, z, DI, DM,
                      by * 128, bx * 128, nullptr, nullptr, 0, nullptr, sm);
    }
}

// ---------------- fused weight converts (single launch) ---------------------
// block (32,8). ranges: [0,4096) in_proj cvtT, [4096,6144) out_proj cvtT,
// [6144,6272) dt cvtT, [6272,6464) x_proj tf32 cvt (flat).
__device__ __forceinline__ void cvtT_body(const float* __restrict__ in,
                                          __half* __restrict__ out,
                                          int R, int C, int bx, int by) {
    __shared__ float tile[32][33];
    int c0 = bx * 32, r0 = by * 32;
    #pragma unroll
    for (int j = 0; j < 32; j += 8)
        tile[threadIdx.y + j][threadIdx.x] =
            in[(size_t)(r0 + threadIdx.y + j) * C + c0 + threadIdx.x];
    __syncthreads();
    #pragma unroll
    for (int j = 0; j < 32; j += 8)
        out[(size_t)(c0 + threadIdx.y + j) * R + r0 + threadIdx.x] =
            __float2half_rn(tile[threadIdx.x][threadIdx.y + j]);
}

__global__ void cvt_all_kernel(const float* __restrict__ in_proj_w,
                               const float* __restrict__ out_proj_w,
                               const float* __restrict__ dt_proj_w,
                               const float* __restrict__ x_proj_w,
                               __half* __restrict__ w_in16,
                               __half* __restrict__ w_out16,
                               __half* __restrict__ w_dt16,
                               float* __restrict__ w_x) {
    int id = blockIdx.x;
    if (id < 4096) {
        cvtT_body(in_proj_w, w_in16, DM, 2 * DI, id & 127, id >> 7);
    } else if (id < 6144) {
        int i2 = id - 4096;
        cvtT_body(out_proj_w, w_out16, DI, DM, i2 & 31, i2 >> 5);
    } else if (id < 6272) {
        int i3 = id - 6144;
        cvtT_body(dt_proj_w, w_dt16, RDT, DI, i3 & 63, i3 >> 6);
    } else {
        int i4 = id - 6272;
        int tid = threadIdx.y * 32 + threadIdx.x;
        int i = (i4 * 256 + tid) * 4;
        if (i < DI * XPW) {
            float4 v = *reinterpret_cast<const float4*>(x_proj_w + i);
            uint4 u = make_uint4(f2tf(v.x), f2tf(v.y), f2tf(v.z), f2tf(v.w));
            *reinterpret_cast<uint4*>(w_x + i) = u;
        }
    }
}

// ---------------- LayerNorm (emits half) -------------------------------------
__global__ void ln_kernel(const float* __restrict__ x,
                          const float* __restrict__ w,
                          const float* __restrict__ b,
                          __half* __restrict__ xn16) {
    int row = blockIdx.x;
    const float4* px = reinterpret_cast<const float4*>(x + (size_t)row * DM);
    float4 v = px[threadIdx.x];
    float s  = v.x + v.y + v.z + v.w;
    float sq = v.x*v.x + v.y*v.y + v.z*v.z + v.w*v.w;
    #pragma unroll
    for (int o = 16; o; o >>= 1) {
        s  += __shfl_xor_sync(0xffffffffu, s,  o);
        sq += __shfl_xor_sync(0xffffffffu, sq, o);
    }
    __shared__ float ss[8], sqs[8];
    __shared__ float s_mu, s_rs;
    int wid = threadIdx.x >> 5, lid = threadIdx.x & 31;
    if (lid == 0) { ss[wid] = s; sqs[wid] = sq; }
    __syncthreads();
    if (threadIdx.x == 0) {
        float S = 0.f, Q = 0.f;
        #pragma unroll
        for (int i = 0; i < 8; i++) { S += ss[i]; Q += sqs[i]; }
        float m = S * (1.0f / DM);
        float var = Q * (1.0f / DM) - m * m;
        s_mu = m;
        s_rs = rsqrtf(var + 1e-5f);
    }
    __syncthreads();
    float m = s_mu, r = s_rs;
    float4 wv = reinterpret_cast<const float4*>(w)[threadIdx.x];
    float4 bv = reinterpret_cast<const float4*>(b)[threadIdx.x];
    __half2 h01 = __floats2half2_rn((v.x - m) * r * wv.x + bv.x,
                                    (v.y - m) * r * wv.y + bv.y);
    __half2 h23 = __floats2half2_rn((v.z - m) * r * wv.z + bv.z,
                                    (v.w - m) * r * wv.w + bv.w);
    uint2 st;
    st.x = *reinterpret_cast<uint32_t*>(&h01);
    st.y = *reinterpret_cast<uint32_t*>(&h23);
    *reinterpret_cast<uint2*>(xn16 + (size_t)row * DM + threadIdx.x * 4) = st;
}

// ---------------- x_proj split-K kernel (tf32, xcT pre-rounded) --------------
__global__ void __launch_bounds__(256, 2)
xproj_kernel(const float* __restrict__ xcT,
             const float* __restrict__ Wx,
             float* __restrict__ part) {
    constexpr int BK = 16, SAT = 136, SBX = 104;
    constexpr int ASZ = BK * SAT, BSZ = BK * SBX;
    __shared__ float At[3 * ASZ];
    __shared__ float Bt[3 * BSZ];

    const int tid  = threadIdx.x;
    const int lane = tid & 31;
    const int wid  = tid >> 5;
    const int wm0 = (wid >> 2) * 64;
    const int wn0 = (wid & 3) * 24;
    const int g = lane >> 2, t = lane & 3;

    const int tok0 = blockIdx.x * 128;
    const int kbase = blockIdx.y * (DI / 4);

    uint32_t aSm = (uint32_t)__cvta_generic_to_shared(At);
    uint32_t bSm = (uint32_t)__cvta_generic_to_shared(Bt);

    auto issueCopy = [&](int st, int k0) {
        int kg = kbase + k0;
        #pragma unroll
        for (int p = 0; p < 2; p++) {
            int idx = tid + p * 256;
            int r = idx >> 5, c = idx & 31;
            CP16(aSm + (uint32_t)(st * ASZ + r * SAT + c * 4) * 4,
                 xcT + (size_t)(kg + r) * MROWS + tok0 + c * 4);
        }
        #pragma unroll
        for (int p = 0; p < 2; p++) {
            int idx = tid + p * 256;
            if (idx < 384) {
                int r = idx / 24, c = idx % 24;
                CP16(bSm + (uint32_t)(st * BSZ + r * SBX + c * 4) * 4,
                     Wx + (size_t)(kg + r) * XPW + c * 4);
            }
        }
        asm volatile("cp.async.commit_group;");
    };

    float acc[4][3][4];
    #pragma unroll
    for (int mi = 0; mi < 4; mi++)
        #pragma unroll
        for (int ni = 0; ni < 3; ni++)
            #pragma unroll
            for (int e = 0; e < 4; e++) acc[mi][ni][e] = 0.f;

    const int nk = (DI / 4) / BK;
    issueCopy(0, 0);
    issueCopy(1, BK);

    for (int kt = 0; kt < nk; kt++) {
        if (kt + 1 < nk)
            asm volatile("cp.async.wait_group 1;");
        else
            asm volatile("cp.async.wait_group 0;");
        __syncthreads();
        if (kt + 2 < nk) issueCopy((kt + 2) % 3, (kt + 2) * BK);

        const float* Af = At + (kt % 3) * ASZ;
        const float* Bf = Bt + (kt % 3) * BSZ;
        #pragma unroll
        for (int ks = 0; ks < 2; ks++) {
            uint32_t af[4][4], bf[3][2];
            #pragma unroll
            for (int mi = 0; mi < 4; mi++) {
                const float* pa = Af + (ks * 8 + t) * SAT + wm0 + mi * 16 + g;
                af[mi][0] = __float_as_uint(pa[0]);
                af[mi][1] = __float_as_uint(pa[8]);
                af[mi][2] = __float_as_uint(pa[4 * SAT]);
                af[mi][3] = __float_as_uint(pa[4 * SAT + 8]);
            }
            #pragma unroll
            for (int ni = 0; ni < 3; ni++) {
                const float* pb = Bf + (ks * 8 + t) * SBX + wn0 + ni * 8 + g;
                bf[ni][0] = __float_as_uint(pb[0]);
                bf[ni][1] = __float_as_uint(pb[4 * SBX]);
            }
            #pragma unroll
            for (int mi = 0; mi < 4; mi++)
                #pragma unroll
                for (int ni = 0; ni < 3; ni++)
                    asm volatile(
                        "mma.sync.aligned.m16n8k8.row.col.f32.tf32.tf32.f32 "
                        "{%0,%1,%2,%3}, {%4,%5,%6,%7}, {%8,%9}, {%0,%1,%2,%3};"
                        : "+f"(acc[mi][ni][0]), "+f"(acc[mi][ni][1]),
                          "+f"(acc[mi][ni][2]), "+f"(acc[mi][ni][3])
                        : "r"(af[mi][0]), "r"(af[mi][1]),
                          "r"(af[mi][2]), "r"(af[mi][3]),
                          "r"(bf[ni][0]), "r"(bf[ni][1]));
        }
        __syncthreads();
    }

    float* po = part + (size_t)blockIdx.y * MROWS * XPW;
    #pragma unroll
    for (int mi = 0; mi < 4; mi++) {
        int r0 = tok0 + wm0 + mi * 16 + g;
        #pragma unroll
        for (int ni = 0; ni < 3; ni++) {
            int c0n = wn0 + ni * 8 + t * 2;
            #pragma unroll
            for (int e = 0; e < 4; e++) {
                int rr = r0 + ((e >= 2) ? 8 : 0);
                int cc = c0n + (e & 1);
                po[(size_t)rr * XPW + cc] = acc[mi][ni][e];
            }
        }
    }
}

// ---------------- reduce 4 x_proj partials -----------------------------------
__global__ void xdbl_reduce_kernel(const float* __restrict__ part,
                                   float* __restrict__ xdbl,
                                   __half* __restrict__ xdbl16) {
    constexpr size_t N4 = (size_t)MROWS * XPW / 4;
    size_t i = (size_t)blockIdx.x * 256 + threadIdx.x;
    if (i < N4) {
        const float4* p = reinterpret_cast<const float4*>(part);
        float4 a = p[i], b = p[i + N4], c = p[i + 2 * N4], d = p[i + 3 * N4];
        float4 r = make_float4(a.x + b.x + c.x + d.x, a.y + b.y + c.y + d.y,
                               a.z + b.z + c.z + d.z, a.w + b.w + c.w + d.w);
        reinterpret_cast<float4*>(xdbl)[i] = r;
        size_t row = (i * 4) / XPW;
        int col = (int)((i * 4) % XPW);
        if (col < RDT) {
            __half2 h01 = __floats2half2_rn(r.x, r.y);
            __half2 h23 = __floats2half2_rn(r.z, r.w);
            uint2 st;
            st.x = *reinterpret_cast<uint32_t*>(&h01);
            st.y = *reinterpret_cast<uint32_t*>(&h23);
            *reinterpret_cast<uint2*>(xdbl16 + row * RDT + col) = st;
        }
    }
}

// ---------------- depthwise causal conv: emits tf32-rounded xcT --------------
__global__ void conv_silu_kernel(const float* __restrict__ in,
                                 float* __restrict__ out,
                                 const float* __restrict__ cw,
                                 const float* __restrict__ cb,
                                 float* __restrict__ outp) {
    int chb = blockIdx.x;
    int d  = chb / BBATCH;
    int b  = chb % BBATCH;
    const float* pin = in + (size_t)d * MROWS + b * LL;
    float* pout = out + (size_t)d * MROWS + b * LL;
    float w0 = cw[d * 4 + 0], w1 = cw[d * 4 + 1], w2 = cw[d * 4 + 2], w3 = cw[d * 4 + 3];
    float bias = cb[d];
    for (int base = threadIdx.x * 4; base < LL; base += blockDim.x * 4) {
        float4 cur = *reinterpret_cast<const float4*>(pin + base);
        float4 prev = (base >= 4) ? *reinterpret_cast<const float4*>(pin + base - 4)
                                  : make_float4(0.f, 0.f, 0.f, 0.f);
        float o0 = bias + w0 * prev.y + w1 * prev.z + w2 * prev.w + w3 * cur.x;
        float o1 = bias + w0 * prev.z + w1 * prev.w + w2 * cur.x + w3 * cur.y;
        float o2 = bias + w0 * prev.w + w1 * cur.x + w2 * cur.y + w3 * cur.z;
        float o3 = bias + w0 * cur.x  + w1 * cur.y + w2 * cur.z + w3 * cur.w;
        uint4 st = make_uint4(f2tf(siluf(o0)), f2tf(siluf(o1)),
                              f2tf(siluf(o2)), f2tf(siluf(o3)));
        *reinterpret_cast<uint4*>(pout + base) = st;
    }
    if (threadIdx.x < 3)
        outp[OOUT_CONV + ((size_t)b * DI + d) * 3 + threadIdx.x] = pin[LL - 3 + threadIdx.x];
}

// ---------------- chunked scan common helpers -------------------------------
struct ScanCtx {
    float A0, A1;
    bool fastok;
    bool b1, b2, b4;
};

__device__ __forceinline__ ScanCtx scan_ctx(const float* A_log, int d, int sub) {
    ScanCtx c;
    float2 Al = *reinterpret_cast<const float2*>(&A_log[d * NSTATE + sub * 2]);
    float a0e = __expf(Al.x);
    float a1e = __expf(Al.y);
    c.A0 = -a0e; c.A1 = -a1e;
    float fi0 = (float)(2 * sub + 1);
    bool ok = (fabsf(a0e - fi0) < 1e-4f) && (fabsf(a1e - (fi0 + 1.0f)) < 1e-4f);
    c.fastok = __all_sync(0xffffffffu, ok);
    c.b1 = (sub & 1); c.b2 = (sub & 2); c.b4 = (sub & 4);
    return c;
}

__device__ __forceinline__ void scan_da(const ScanCtx& c, float dt,
                                        float& da0, float& da1) {
    if (c.fastok) {
        float E  = __expf(-dt);
        float E2 = E * E;
        float E4 = E2 * E2;
        float E8 = E4 * E4;
        float q = E;
        if (c.b1) q *= E2;
        if (c.b2) q *= E4;
        if (c.b4) q *= E8;
        da0 = q;
        da1 = q * E;
    } else {
        da0 = __expf(c.A0 * dt);
        da1 = __expf(c.A1 * dt);
    }
}

// ---------------- scan phase 1 ------------------------------------------------
__global__ void __launch_bounds__(256)
scan_phase1(const float* __restrict__ dtT, const float* __restrict__ xT,
            const float* __restrict__ xdbl, const float* __restrict__ A_log,
            float* __restrict__ aprod, float* __restrict__ bst) {
    int tid = threadIdx.x;
    int ch  = blockIdx.x * 32 + (tid >> 3);
    int sub = tid & 7;
    int ck  = blockIdx.y;
    int b   = ch / DI;
    int d   = ch & (DI - 1);
    ScanCtx cx = scan_ctx(A_log, d, sub);

    const float* pdt = dtT + (size_t)d * MROWS + b * LL + ck * CLEN;
    const float* px  = xT  + (size_t)d * MROWS + b * LL + ck * CLEN;
    const float* pbc = xdbl + ((size_t)b * LL + ck * CLEN) * XPW;

    float h0 = 0.f, h1 = 0.f, ap0 = 1.f, ap1 = 1.f;
    for (int t0 = 0; t0 < CLEN; t0 += 8) {
        float4 dtA = *reinterpret_cast<const float4*>(pdt + t0);
        float4 dtB = *reinterpret_cast<const float4*>(pdt + t0 + 4);
        float4 xvA = *reinterpret_cast<const float4*>(px + t0);
        float4 xvB = *reinterpret_cast<const float4*>(px + t0 + 4);
        float dts[8] = {dtA.x, dtA.y, dtA.z, dtA.w, dtB.x, dtB.y, dtB.z, dtB.w};
        float xvs[8] = {xvA.x, xvA.y, xvA.z, xvA.w, xvB.x, xvB.y, xvB.z, xvB.w};
        #pragma unroll
        for (int j = 0; j < 8; j++) {
            float dt = dts[j];
            const float* prow = pbc + (size_t)(t0 + j) * XPW;
            float2 Bv = *reinterpret_cast<const float2*>(prow + RDT + sub * 2);
            float da0, da1;
            scan_da(cx, dt, da0, da1);
            float dx = dt * xvs[j];
            h0 = fmaf(da0, h0, Bv.x * dx);
            h1 = fmaf(da1, h1, Bv.y * dx);
            ap0 *= da0;
            ap1 *= da1;
        }
    }
    size_t o = ((size_t)ch * NCH + ck) * NSTATE + sub * 2;
    *reinterpret_cast<float2*>(bst + o)   = make_float2(h0, h1);
    *reinterpret_cast<float2*>(aprod + o) = make_float2(ap0, ap1);
}

// ---------------- scan phase 2 ------------------------------------------------
__global__ void scan_phase2(const float* __restrict__ aprod,
                            const float* __restrict__ bst,
                            float* __restrict__ hin) {
    int idx = blockIdx.x * 256 + threadIdx.x;
    if (idx < BBATCH * DI * NSTATE) {
        int ch = idx >> 4;
        int n  = idx & 15;
        float h = 0.f;
        #pragma unroll
        for (int c = 0; c < NCH; c++) {
            size_t o = ((size_t)ch * NCH + c) * NSTATE + n;
            hin[o] = h;
            h = fmaf(aprod[o], h, bst[o]);
        }
    }
}

// ---------------- scan phase 3: seeded scan + fused gate ----------------------
__global__ void __launch_bounds__(256)
scan_phase3(const float* __restrict__ dtT, const float* __restrict__ xT,
            const float* __restrict__ xdbl, const float* __restrict__ A_log,
            const float* __restrict__ hin, const float* __restrict__ Dp,
            const float* __restrict__ z,
            __half* __restrict__ yy16, float* __restrict__ outp) {
    __shared__ float ysm[32][33];
    __shared__ float xsm[32][33];
    __shared__ float dsm[32];

    int tid = threadIdx.x;
    int cl  = tid >> 3;
    int sub = tid & 7;
    int ck  = blockIdx.y;
    int chBase = blockIdx.x * 32;
    int ch  = chBase + cl;
    int b   = ch / DI;
    int d   = ch & (DI - 1);
    int d0  = chBase & (DI - 1);
    ScanCtx cx = scan_ctx(A_log, d, sub);

    if (tid < 32) dsm[tid] = Dp[d0 + tid];

    const float* pdt = dtT + (size_t)d * MROWS + b * LL + ck * CLEN;
    const float* px  = xT  + (size_t)d * MROWS + b * LL + ck * CLEN;
    const float* pbc = xdbl + ((size_t)b * LL + ck * CLEN) * XPW;

    float2 h = *reinterpret_cast<const float2*>(
        hin + ((size_t)ch * NCH + ck) * NSTATE + sub * 2);
    float h0 = h.x, h1 = h.y;
    __syncthreads();

    for (int tb = 0; tb < CLEN; tb += 32) {
        #pragma unroll
        for (int g8 = 0; g8 < 4; g8++) {
            int t0 = tb + g8 * 8;
            float4 dtA = *reinterpret_cast<const float4*>(pdt + t0);
            float4 dtB = *reinterpret_cast<const float4*>(pdt + t0 + 4);
            float4 xvA = *reinterpret_cast<const float4*>(px + t0);
            float4 xvB = *reinterpret_cast<const float4*>(px + t0 + 4);
            float dts[8] = {dtA.x, dtA.y, dtA.z, dtA.w, dtB.x, dtB.y, dtB.z, dtB.w};
            float xvs[8] = {xvA.x, xvA.y, xvA.z, xvA.w, xvB.x, xvB.y, xvB.z, xvB.w};
            float pj[8];
            #pragma unroll
            for (int j = 0; j < 8; j++) {
                float dt = dts[j];
                const float* prow = pbc + (size_t)(t0 + j) * XPW;
                float2 Bv = *reinterpret_cast<const float2*>(prow + RDT + sub * 2);
                float2 Cv = *reinterpret_cast<const float2*>(prow + RDT + NSTATE + sub * 2);
                float da0, da1;
                scan_da(cx, dt, da0, da1);
                float dx = dt * xvs[j];
                h0 = fmaf(da0, h0, Bv.x * dx);
                h1 = fmaf(da1, h1, Bv.y * dx);
                pj[j] = fmaf(h0, Cv.x, h1 * Cv.y);
            }
            #pragma unroll
            for (int off = 4; off; off >>= 1)
                #pragma unroll
                for (int j = 0; j < 8; j++)
                    pj[j] += __shfl_xor_sync(0xffffffffu, pj[j], off, 8);
            if (sub == 0) {
                int r = g8 * 8;
                #pragma unroll
                for (int j = 0; j < 8; j++) {
                    ysm[r + j][cl] = pj[j];
                    xsm[r + j][cl] = xvs[j];
                }
            }
        }
        __syncthreads();
        {
            int r = tid >> 3;
            int c = (tid & 7) * 4;
            size_t row = (size_t)b * LL + ck * CLEN + tb + r;
            float4 z4 = *reinterpret_cast<const float4*>(z + row * DI + d0 + c);
            float v0 = (ysm[r][c + 0] + xsm[r][c + 0] * dsm[c + 0]) * siluf(z4.x);
            float v1 = (ysm[r][c + 1] + xsm[r][c + 1] * dsm[c + 1]) * siluf(z4.y);
            float v2 = (ysm[r][c + 2] + xsm[r][c + 2] * dsm[c + 2]) * siluf(z4.z);
            float v3 = (ysm[r][c + 3] + xsm[r][c + 3] * dsm[c + 3]) * siluf(z4.w);
            __half2 p01 = __floats2half2_rn(v0, v1);
            __half2 p23 = __floats2half2_rn(v2, v3);
            uint2 st;
            st.x = *reinterpret_cast<uint32_t*>(&p01);
            st.y = *reinterpret_cast<uint32_t*>(&p23);
            *reinterpret_cast<uint2*>(yy16 + row * DI + d0 + c) = st;
        }
        __syncthreads();
    }
    if (ck == NCH - 1)
        *reinterpret_cast<float2*>(&outp[OOUT_SSM + (size_t)ch * NSTATE + sub * 2]) =
            make_float2(h0, h1);
}

// ---------------- launch ----------------------------------------------------
extern "C" void kernel_launch(void* const* d_in, const int* in_sizes, int n_in,
                              void* d_out, int out_size) {
    const float* x         = (const float*)d_in[0];
    const float* ln_w      = (const float*)d_in[1];
    const float* ln_b      = (const float*)d_in[2];
    const float* in_proj_w = (const float*)d_in[3];
    const float* conv_w    = (const float*)d_in[4];
    const float* conv_b    = (const float*)d_in[5];
    const float* x_proj_w  = (const float*)d_in[6];
    const float* dt_proj_w = (const float*)d_in[7];
    const float* dt_proj_b = (const float*)d_in[8];
    const float* A_log     = (const float*)d_in[9];
    const float* D_param   = (const float*)d_in[10];
    const float* out_proj_w= (const float*)d_in[11];
    const float* res_scale = (const float*)d_in[12];
    float* out = (float*)d_out;

    float* S = nullptr;
    cudaGetSymbolAddress((void**)&S, g_scratch);

    float*  z      = S + O_Z;
    float*  xmT    = S + O_XMT;
    float*  xcT    = S + O_XCT;
    float*  dtT    = S + O_DTT;
    float*  xdbl   = S + O_XDBL;
    float*  w_x    = S + O_WX;
    float*  xpart  = S + O_XPART;
    float*  aprod  = S + O_APROD;
    float*  bst    = S + O_BST;
    float*  hin    = S + O_HIN;
    __half* xn16   = (__half*)(S + O_XN16);
    __half* w_in16 = (__half*)(S + O_WIN16);
    __half* w_out16= (__half*)(S + O_WOUT16);
    __half* w_dt16 = (__half*)(S + O_WDT16);
    __half* yy16   = (__half*)(S + O_YY16);
    __half* xdbl16 = (__half*)(S + O_XDBL16);

    const int HSMEM = 81920;
    cudaFuncSetAttribute(hgemm_xz, cudaFuncAttributeMaxDynamicSharedMemorySize, HSMEM);
    cudaFuncSetAttribute(hgemm<2>, cudaFuncAttributeMaxDynamicSharedMemorySize, HSMEM);
    cudaFuncSetAttribute(hgemm<3>, cudaFuncAttributeMaxDynamicSharedMemorySize, HSMEM);

    dim3 tb(32, 8);

    // 1) all weight converts in one launch
    cvt_all_kernel<<<6464, tb>>>(in_proj_w, out_proj_w, dt_proj_w, x_proj_w,
                                 w_in16, w_out16, w_dt16, w_x);
    // 2) LayerNorm (half output)
    ln_kernel<<<MROWS, 256>>>(x, ln_w, ln_b, xn16);

    // 3) fused x-GEMM + z-GEMM (1024 CTAs)   [profiled slot ~4th]
    hgemm_xz<<<1024, 128, HSMEM>>>(xn16, w_in16, xmT, z);

    // 4) conv + silu + conv-state; emits tf32-rounded xcT
    conv_silu_kernel<<<DI * BBATCH, 256>>>(xmT, xcT, conv_w, conv_b, out);

    // 5) x_proj split-K (tf32, no in-loop cvt)
    xproj_kernel<<<dim3(MROWS / 128, 4), 256>>>(xcT, w_x, xpart);

    // 6) reduce partials -> xdbl + xdbl16
    xdbl_reduce_kernel<<<(MROWS * XPW / 4 + 255) / 256, 256>>>(xpart, xdbl, xdbl16);

    // 7) dt-GEMM (transposed output + softplus/bias[row]): dtT[d][token]
    hgemm<3><<<dim3(MROWS / 128, DI / 128), 128, HSMEM>>>(
        w_dt16, RDT, xdbl16, RDT, dtT, MROWS,
        DI, MROWS, RDT, dt_proj_b, nullptr, 0, nullptr);

    // 8) chunked scan: phase1 -> phase2 -> phase3 (+gate)
    scan_phase1<<<dim3((BBATCH * DI) / 32, NCH), 256>>>(
        dtT, xcT, xdbl, A_log, aprod, bst);
    scan_phase2<<<(BBATCH * DI * NSTATE + 255) / 256, 256>>>(aprod, bst, hin);
    scan_phase3<<<dim3((BBATCH * DI) / 32, NCH), 256>>>(
        dtT, xcT, xdbl, A_log, hin, D_param, z, yy16, out);

    // 9) out_proj (fp16 HMMA) + residual
    hgemm<2><<<dim3(DM / 128, MROWS / 128), 128, HSMEM>>>(
        yy16, DI, w_out16, DI, out, DM,
        MROWS, DM, DI, nullptr, x, DM, res_scale);
}